// round 9
// baseline (speedup 1.0000x reference)
#include <cuda_runtime.h>
#include <cuda_bf16.h>
#include <math.h>
#include <stdint.h>

#define B_   2
#define T_   2048
#define D_   512
#define H_   8
#define HD_  64
#define F_   2048
#define M_   (B_*T_)
#define CH_  64
#define NCH_ (T_/CH_)
#define NBH_ (B_*H_)
#define QKVO (NBH_*T_*HD_)      // per-matrix stride inside g_QKV

// ------------------------- scratch globals ---------------------------------
__device__ __nv_bfloat16 g_xnh[M_*D_], g_xnl[M_*D_];
__device__ __nv_bfloat16 g_ath[M_*D_], g_atl[M_*D_];
__device__ __nv_bfloat16 g_h2h[M_*D_], g_h2l[M_*D_];
__device__ __nv_bfloat16 g_f1h[M_*F_], g_f1l[M_*F_];
__device__ __nv_bfloat16 g_wqkvh[3*D_*D_], g_wqkvl[3*D_*D_];  // rows: Wq|Wk|Wv
__device__ __nv_bfloat16 g_woh[D_*D_], g_wol[D_*D_];
__device__ __nv_bfloat16 g_w1h[F_*D_], g_w1l[F_*D_];
__device__ __nv_bfloat16 g_w2h[D_*F_], g_w2l[D_*F_];
__device__ float g_QKV[3*QKVO];                               // Q|K|V  [b,h,t,e]
__device__ float g_Y[2*NBH_*T_*HD_], g_C[2*NBH_*T_];
__device__ float g_x2[M_*D_];
__device__ float g_Schk[2*NBH_*NCH_*HD_*HD_];
__device__ float g_zchk[2*NBH_*NCH_*HD_];

// ------------------------- helpers -----------------------------------------
static __device__ __forceinline__ uint32_t stou(const void* p){
    uint32_t a;
    asm("{ .reg .u64 t; cvta.to.shared.u64 t, %1; cvt.u32.u64 %0, t; }" : "=r"(a) : "l"(p));
    return a;
}
static __device__ __forceinline__ void cp16(uint32_t dst, const void* src){
    asm volatile("cp.async.cg.shared.global [%0], [%1], 16;" :: "r"(dst), "l"(src));
}
static __device__ __forceinline__ void ldmA(uint32_t* a, uint32_t addr){
    asm volatile("ldmatrix.sync.aligned.m8n8.x4.shared.b16 {%0,%1,%2,%3}, [%4];"
        : "=r"(a[0]),"=r"(a[1]),"=r"(a[2]),"=r"(a[3]) : "r"(addr));
}
static __device__ __forceinline__ void ldmB(uint32_t* b, uint32_t addr){
    asm volatile("ldmatrix.sync.aligned.m8n8.x2.shared.b16 {%0,%1}, [%2];"
        : "=r"(b[0]),"=r"(b[1]) : "r"(addr));
}
static __device__ __forceinline__ void mma16816(float* c, const uint32_t* a, const uint32_t* b){
    asm volatile("mma.sync.aligned.m16n8k16.row.col.f32.bf16.bf16.f32 "
        "{%0,%1,%2,%3}, {%4,%5,%6,%7}, {%8,%9}, {%0,%1,%2,%3};"
        : "+f"(c[0]),"+f"(c[1]),"+f"(c[2]),"+f"(c[3])
        : "r"(a[0]),"r"(a[1]),"r"(a[2]),"r"(a[3]), "r"(b[0]),"r"(b[1]));
}

// rows of 64 bf16 padded to 72 (144 bytes)
#define ROWB  144
// 128x128 kernel (validated R8)
#define ATILE 18432            // 128*144
#define STGB  36864
#define GEMM_SMEM (2*STGB)     // 73728
// 128x256 kernel
#define BOFF2  18432           // A region = 128 rows
#define STGB2  55296           // + B 256 rows
#define GEMM2_SMEM (3*STGB2)   // 165888, 3 stages

// ---------------------------------------------------------------------------
// 128x128 split-bf16 GEMM (K'=3K), 2-stage. MODE: 2=bias+res->fp32
// ---------------------------------------------------------------------------
template<int MODE, int KDIM>
__global__ void __launch_bounds__(256,2) tc_gemm(
    const __nv_bfloat16* __restrict__ Ah, const __nv_bfloat16* __restrict__ Al,
    const __nv_bfloat16* __restrict__ Bh, const __nv_bfloat16* __restrict__ Bl,
    int N, const float* __restrict__ bias, const float* __restrict__ res,
    float* __restrict__ outF)
{
    extern __shared__ char dyns[];
    uint32_t sb = stou(dyns);

    int tid = threadIdx.x;
    int lane = tid & 31, w = tid >> 5;
    int warp_m = w >> 2, warp_n = w & 3;
    int m0 = blockIdx.y * 128;
    int n0 = blockIdx.x * 128;

    float acc[4][4][4];
#pragma unroll
    for (int i=0;i<4;i++)
#pragma unroll
        for (int j=0;j<4;j++)
#pragma unroll
            for (int k=0;k<4;k++) acc[i][j][k] = 0.f;

    const int NIT = 3*KDIM/64;

    auto fill = [&](int itf){
        int st = itf & 1;
        int kp = itf * 64;
        int pass = kp / KDIM;
        int koff = kp - pass*KDIM;
        const __nv_bfloat16* pA = (pass==1)? Al : Ah;
        const __nv_bfloat16* pB = (pass==2)? Bl : Bh;
        uint32_t base = sb + st*STGB;
#pragma unroll
        for (int i=0;i<8;i++){
            int q = tid + i*256;
            int isB = q >> 10;
            int r   = (q >> 3) & 127;
            int c16 = q & 7;
            const __nv_bfloat16* src =
                (isB ? (pB + (size_t)(n0+r)*KDIM) : (pA + (size_t)(m0+r)*KDIM)) + koff + c16*8;
            cp16(base + isB*ATILE + r*ROWB + c16*16, src);
        }
        asm volatile("cp.async.commit_group;" ::: "memory");
    };

    uint32_t aBase = (uint32_t)((warp_m*64 + (lane & 15))*ROWB + ((lane >> 4) << 4));
    uint32_t bBase = (uint32_t)(ATILE + (warp_n*32 + (lane & 7))*ROWB + (((lane >> 3) & 1) << 4));

    fill(0);
    for (int it=0; it<NIT; ++it){
        if (it+1 < NIT){
            fill(it+1);
            asm volatile("cp.async.wait_group 1;" ::: "memory");
        } else {
            asm volatile("cp.async.wait_group 0;" ::: "memory");
        }
        __syncthreads();
        uint32_t stg = sb + (it&1)*STGB;
#pragma unroll
        for (int kk=0; kk<64; kk+=16){
            uint32_t afrag[4][4], bfrag[4][2];
#pragma unroll
            for (int mt=0;mt<4;mt++) ldmA(afrag[mt], stg + aBase + mt*(16*ROWB) + kk*2);
#pragma unroll
            for (int nt=0;nt<4;nt++) ldmB(bfrag[nt], stg + bBase + nt*(8*ROWB) + kk*2);
#pragma unroll
            for (int mt=0;mt<4;mt++)
#pragma unroll
                for (int nt=0;nt<4;nt++) mma16816(acc[mt][nt], afrag[mt], bfrag[nt]);
        }
        __syncthreads();
    }

    int mb = m0 + warp_m*64;
    int nb = n0 + warp_n*32;
#pragma unroll
    for (int mt=0; mt<4; mt++){
#pragma unroll
        for (int half=0; half<2; half++){
            int m = mb + mt*16 + (lane>>2) + half*8;
#pragma unroll
            for (int nt=0; nt<4; nt++){
                int n = nb + nt*8 + (lane&3)*2;
                float v0 = acc[mt][nt][half*2];
                float v1 = acc[mt][nt][half*2+1];
                size_t idx = (size_t)m*N + n;
                float2 rv = *(const float2*)(res + idx);
                float2 o;
                o.x = v0 + bias[n]   + rv.x;
                o.y = v1 + bias[n+1] + rv.y;
                *(float2*)(outF + idx) = o;
            }
        }
    }
}

// ---------------------------------------------------------------------------
// 128x256 split-bf16 GEMM, warp tile 64x64, 3-stage, 1 sync/iter.
// MODE: 0 = QKV fused scatter (elu for n<1024), 3 = bias+gelu -> split bf16
// ---------------------------------------------------------------------------
template<int MODE, int KDIM>
__global__ void __launch_bounds__(256,1) tc_gemm_big(
    const __nv_bfloat16* __restrict__ Ah, const __nv_bfloat16* __restrict__ Al,
    const __nv_bfloat16* __restrict__ Bh, const __nv_bfloat16* __restrict__ Bl,
    int N, const float* __restrict__ bias,
    float* __restrict__ outF,
    __nv_bfloat16* __restrict__ outH, __nv_bfloat16* __restrict__ outL)
{
    extern __shared__ char dyns[];
    uint32_t sb = stou(dyns);

    int tid = threadIdx.x;
    int lane = tid & 31, w = tid >> 5;
    int warp_m = w >> 2;          // 0..1
    int warp_n = w & 3;           // 0..3
    int m0 = blockIdx.y * 128;
    int n0 = blockIdx.x * 256;

    float acc[4][8][4];
#pragma unroll
    for (int i=0;i<4;i++)
#pragma unroll
        for (int j=0;j<8;j++)
#pragma unroll
            for (int k=0;k<4;k++) acc[i][j][k] = 0.f;

    const int NIT = 3*KDIM/64;

    auto fill = [&](int itf){
        int st = itf % 3;
        int kp = itf * 64;
        int pass = kp / KDIM;
        int koff = kp - pass*KDIM;
        const __nv_bfloat16* pA = (pass==1)? Al : Ah;
        const __nv_bfloat16* pB = (pass==2)? Bl : Bh;
        uint32_t base = sb + st*STGB2;
#pragma unroll
        for (int i=0;i<12;i++){
            int q = tid + i*256;           // 0..3071
            if (q < 1024){
                int r = q >> 3, c16 = q & 7;
                cp16(base + r*ROWB + c16*16,
                     pA + (size_t)(m0+r)*KDIM + koff + c16*8);
            } else {
                int q2 = q - 1024;
                int r = q2 >> 3, c16 = q2 & 7;
                cp16(base + BOFF2 + r*ROWB + c16*16,
                     pB + (size_t)(n0+r)*KDIM + koff + c16*8);
            }
        }
        asm volatile("cp.async.commit_group;" ::: "memory");
    };

    uint32_t aBase = (uint32_t)((warp_m*64 + (lane & 15))*ROWB + ((lane >> 4) << 4));
    uint32_t bBase = (uint32_t)(BOFF2 + (warp_n*64 + (lane & 7))*ROWB + (((lane >> 3) & 1) << 4));

    fill(0); fill(1);
    for (int it=0; it<NIT; ++it){
        if (it+1 < NIT) asm volatile("cp.async.wait_group 1;" ::: "memory");
        else            asm volatile("cp.async.wait_group 0;" ::: "memory");
        __syncthreads();
        if (it+2 < NIT) fill(it+2);       // writes stage computed at it-1 (safe: barrier passed)
        uint32_t stg = sb + (it%3)*STGB2;
#pragma unroll
        for (int kk=0; kk<64; kk+=16){
            uint32_t afrag[4][4], bfrag[8][2];
#pragma unroll
            for (int mt=0;mt<4;mt++) ldmA(afrag[mt], stg + aBase + mt*(16*ROWB) + kk*2);
#pragma unroll
            for (int nt=0;nt<8;nt++) ldmB(bfrag[nt], stg + bBase + nt*(8*ROWB) + kk*2);
#pragma unroll
            for (int mt=0;mt<4;mt++)
#pragma unroll
                for (int nt=0;nt<8;nt++) mma16816(acc[mt][nt], afrag[mt], bfrag[nt]);
        }
    }

    int mb = m0 + warp_m*64;
    int nb = n0 + warp_n*64;
#pragma unroll
    for (int mt=0; mt<4; mt++){
#pragma unroll
        for (int half=0; half<2; half++){
            int m = mb + mt*16 + (lane>>2) + half*8;
            int bb = m >> 11, tt = m & (T_-1);
#pragma unroll
            for (int nt=0; nt<8; nt++){
                int n = nb + nt*8 + (lane&3)*2;
                float v0 = acc[mt][nt][half*2];
                float v1 = acc[mt][nt][half*2+1];
                if (MODE == 0){
                    int mat = n >> 9;              // 0=Q 1=K 2=V
                    if (mat < 2){
                        v0 = v0>0.f ? v0+1.f : expf(v0);
                        v1 = v1>0.f ? v1+1.f : expf(v1);
                    }
                    int hh = (n >> 6) & 7, ee = n & 63;
                    float* dst = outF + (size_t)mat*QKVO
                               + ((((size_t)(bb*H_ + hh))*T_ + tt)<<6) + ee;
                    float2 o; o.x=v0; o.y=v1;
                    *(float2*)dst = o;
                } else {   // MODE 3: bias + exact GELU -> split bf16
                    size_t idx = (size_t)m*N + n;
                    float a = v0 + bias[n];
                    float b = v1 + bias[n+1];
                    a = 0.5f*a*(1.f+erff(a*0.70710678118654752f));
                    b = 0.5f*b*(1.f+erff(b*0.70710678118654752f));
                    __nv_bfloat16 ha=__float2bfloat16(a), hb=__float2bfloat16(b);
                    float la = a-__bfloat162float(ha), lb = b-__bfloat162float(hb);
                    uint32_t hp = (uint32_t)__bfloat16_as_ushort(ha) |
                                  ((uint32_t)__bfloat16_as_ushort(hb)<<16);
                    uint32_t lp = (uint32_t)__bfloat16_as_ushort(__float2bfloat16(la)) |
                                  ((uint32_t)__bfloat16_as_ushort(__float2bfloat16(lb))<<16);
                    *(uint32_t*)(outH + idx) = hp;
                    *(uint32_t*)(outL + idx) = lp;
                }
            }
        }
    }
}

// ------------------------- batched weight split ------------------------------
// layout: [Wq|Wk|Wv](786432 -> qkv) [Wo](262144) [W1](1048576) [W2](1048576)
__global__ void __launch_bounds__(256) split_all_kernel(
    const float* __restrict__ Wq, const float* __restrict__ Wk,
    const float* __restrict__ Wv, const float* __restrict__ Wo,
    const float* __restrict__ W1, const float* __restrict__ W2)
{
    int i = blockIdx.x * 256 + threadIdx.x;
    float v; __nv_bfloat16 *dh, *dl; int j;
    if (i < 786432){
        int which = i >> 18; j = i & 262143;
        v = (which==0 ? Wq : which==1 ? Wk : Wv)[j];
        dh = g_wqkvh + i; dl = g_wqkvl + i;
    } else if (i < 1048576){
        j = i - 786432; v = Wo[j]; dh = g_woh + j; dl = g_wol + j;
    } else if (i < 2097152){
        j = i - 1048576; v = W1[j]; dh = g_w1h + j; dl = g_w1l + j;
    } else {
        j = i - 2097152; v = W2[j]; dh = g_w2h + j; dl = g_w2l + j;
    }
    __nv_bfloat16 hh = __float2bfloat16(v);
    *dh = hh;
    *dl = __float2bfloat16(v - __bfloat162float(hh));
}

// ------------------------- LayerNorm + split --------------------------------
__global__ void __launch_bounds__(256) ln_split_kernel(
    const float* __restrict__ x, const float* __restrict__ g,
    const float* __restrict__ b, __nv_bfloat16* __restrict__ yh,
    __nv_bfloat16* __restrict__ yl)
{
    int row = blockIdx.x;
    const float* xr = x + (size_t)row * D_;
    int tid = threadIdx.x;
    float v0 = xr[tid], v1 = xr[tid + 256];
    float s  = v0 + v1, ss = v0*v0 + v1*v1;
    __shared__ float sh[16];
#pragma unroll
    for (int o = 16; o; o >>= 1) {
        s  += __shfl_xor_sync(0xffffffffu, s,  o);
        ss += __shfl_xor_sync(0xffffffffu, ss, o);
    }
    int w = tid >> 5;
    if ((tid & 31) == 0) { sh[w] = s; sh[w + 8] = ss; }
    __syncthreads();
    float S = 0.f, SS = 0.f;
#pragma unroll
    for (int i = 0; i < 8; i++) { S += sh[i]; SS += sh[8 + i]; }
    float mean = S * (1.0f / D_);
    float rstd = rsqrtf(SS * (1.0f / D_) - mean*mean + 1e-5f);
    size_t base = (size_t)row * D_;
    float o0 = (v0 - mean) * rstd * g[tid]       + b[tid];
    float o1 = (v1 - mean) * rstd * g[tid + 256] + b[tid + 256];
    __nv_bfloat16 h0 = __float2bfloat16(o0), h1 = __float2bfloat16(o1);
    yh[base + tid]       = h0;
    yh[base + tid + 256] = h1;
    yl[base + tid]       = __float2bfloat16(o0 - __bfloat162float(h0));
    yl[base + tid + 256] = __float2bfloat16(o1 - __bfloat162float(h1));
}

// ------------------------- recurrence (validated R5) ------------------------
__global__ void __launch_bounds__(256) scan_kernel(const float* __restrict__ dlogit)
{
    int bx  = blockIdx.x;
    int eq  = bx & 3;
    int bh  = (bx >> 2) & 15;
    int dir = bx >> 6;
    int h   = bh & 7;
    float lam  = 1.f / (1.f + expf(-dlogit[h]));
    float lamC = powf(lam, (float)CH_);

    __shared__ float sK[CH_ * HD_];
    __shared__ float sV[CH_ * HD_];
    __shared__ float w [CH_];

    int tid = threadIdx.x;
    int d = tid & 63;
    int c = tid >> 6;
    int ebase = eq * 16 + c * 4;
    if (tid < CH_) w[tid] = powf(lam, (float)(CH_ - 1 - tid));

    float S0=0.f,S1=0.f,S2=0.f,S3=0.f,z=0.f;
    const float* Kg = g_QKV + QKVO   + (size_t)bh * T_ * HD_;
    const float* Vg = g_QKV + 2*QKVO + (size_t)bh * T_ * HD_;
    float* Sout = g_Schk + (size_t)(dir * NBH_ + bh) * NCH_ * (HD_ * HD_);
    float* zout = g_zchk + (size_t)(dir * NBH_ + bh) * NCH_ * HD_;

    int lrow = tid >> 2;
    int lseg = (tid & 3) * 16;

    for (int j = 0; j < NCH_; j++) {
        size_t sbx = (size_t)j * (HD_ * HD_);
        Sout[sbx + (ebase + 0) * 64 + d] = S0;
        Sout[sbx + (ebase + 1) * 64 + d] = S1;
        Sout[sbx + (ebase + 2) * 64 + d] = S2;
        Sout[sbx + (ebase + 3) * 64 + d] = S3;
        if (eq == 0 && c == 0) zout[j * 64 + d] = z;

        int pt = dir ? (T_ - 1 - (j * CH_ + lrow)) : (j * CH_ + lrow);
        const float4* krow = (const float4*)(Kg + (size_t)pt * HD_ + lseg);
        const float4* vrow = (const float4*)(Vg + (size_t)pt * HD_ + lseg);
        __syncthreads();
        {
            float4* skr = (float4*)(sK + lrow * HD_ + lseg);
            float4* svr = (float4*)(sV + lrow * HD_ + lseg);
            skr[0]=krow[0]; skr[1]=krow[1]; skr[2]=krow[2]; skr[3]=krow[3];
            svr[0]=vrow[0]; svr[1]=vrow[1]; svr[2]=vrow[2]; svr[3]=vrow[3];
        }
        __syncthreads();

        S0 *= lamC; S1 *= lamC; S2 *= lamC; S3 *= lamC; z *= lamC;
#pragma unroll 8
        for (int s = 0; s < CH_; s++) {
            float kk = sK[s * HD_ + d] * w[s];
            float4 vv = *(const float4*)(sV + s * HD_ + ebase);
            S0 = fmaf(kk, vv.x, S0);
            S1 = fmaf(kk, vv.y, S1);
            S2 = fmaf(kk, vv.z, S2);
            S3 = fmaf(kk, vv.w, S3);
            z += kk;
        }
    }
}

#define SOFF_Q   0
#define SOFF_K   4160
#define SOFF_A   8320
#define SOFF_S   12480
#define SOFF_V   16640
#define SOFF_ZP  20736
#define SOFF_DG  20800
#define SOFF_LP  20864
#define P2_SMEM_BYTES ((20864 + 80) * 4)

__global__ void __launch_bounds__(256) chunk_kernel(const float* __restrict__ dlogit)
{
    extern __shared__ float sm[];
    float* sQ  = sm + SOFF_Q;
    float* sK  = sm + SOFF_K;
    float* sA  = sm + SOFF_A;
    float* sS  = sm + SOFF_S;
    float* sV  = sm + SOFF_V;
    float* szp = sm + SOFF_ZP;
    float* sdg = sm + SOFF_DG;
    float* slp = sm + SOFF_LP;

    int bx  = blockIdx.x;
    int j   = bx & 31;
    int bh  = (bx >> 5) & 15;
    int dir = bx >> 9;
    int h   = bh & 7;
    float lam = 1.f / (1.f + expf(-dlogit[h]));

    int tid = threadIdx.x;
    if (tid <= CH_) slp[tid] = powf(lam, (float)tid);

    const float* Qg  = g_QKV            + (size_t)bh * T_ * HD_;
    const float* Kg  = g_QKV + QKVO     + (size_t)bh * T_ * HD_;
    const float* Vg  = g_QKV + 2*QKVO   + (size_t)bh * T_ * HD_;
    const float* Sin = g_Schk + (size_t)((dir * NBH_ + bh) * NCH_ + j) * (HD_ * HD_);
    const float* zin = g_zchk + (size_t)((dir * NBH_ + bh) * NCH_ + j) * HD_;

    int lrow = tid >> 2;
    int lseg = (tid & 3) * 16;
    int pt0 = dir ? (T_ - 1 - (j * CH_ + lrow)) : (j * CH_ + lrow);

#pragma unroll 4
    for (int i = 0; i < 16; i++) {
        sQ[lrow * 65 + lseg + i] = Qg[(size_t)pt0 * HD_ + lseg + i];
        sK[lrow * 65 + lseg + i] = Kg[(size_t)pt0 * HD_ + lseg + i];
    }
    {
        float4* svr = (float4*)(sV + lrow * 64 + lseg);
        const float4* vr = (const float4*)(Vg + (size_t)pt0 * HD_ + lseg);
        svr[0]=vr[0]; svr[1]=vr[1]; svr[2]=vr[2]; svr[3]=vr[3];
    }
#pragma unroll 4
    for (int i = 0; i < 16; i++) {
        int idx = tid * 16 + i;
        int e = idx >> 6, dd = idx & 63;
        sS[e * 65 + dd] = Sin[idx];
    }
    if (tid < 64) szp[tid] = zin[tid];
    __syncthreads();

    {
        int ty = tid >> 4, tx = tid & 15;
        int r0 = ty * 4, c0 = tx * 4;
        float acc[4][4];
#pragma unroll
        for (int i = 0; i < 4; i++)
#pragma unroll
            for (int jc = 0; jc < 4; jc++) acc[i][jc] = 0.f;

        for (int d = 0; d < 64; d++) {
            float q0 = sQ[(r0+0)*65+d], q1 = sQ[(r0+1)*65+d];
            float q2 = sQ[(r0+2)*65+d], q3 = sQ[(r0+3)*65+d];
            float k0 = sK[(c0+0)*65+d], k1 = sK[(c0+1)*65+d];
            float k2 = sK[(c0+2)*65+d], k3 = sK[(c0+3)*65+d];
            acc[0][0]=fmaf(q0,k0,acc[0][0]); acc[0][1]=fmaf(q0,k1,acc[0][1]);
            acc[0][2]=fmaf(q0,k2,acc[0][2]); acc[0][3]=fmaf(q0,k3,acc[0][3]);
            acc[1][0]=fmaf(q1,k0,acc[1][0]); acc[1][1]=fmaf(q1,k1,acc[1][1]);
            acc[1][2]=fmaf(q1,k2,acc[1][2]); acc[1][3]=fmaf(q1,k3,acc[1][3]);
            acc[2][0]=fmaf(q2,k0,acc[2][0]); acc[2][1]=fmaf(q2,k1,acc[2][1]);
            acc[2][2]=fmaf(q2,k2,acc[2][2]); acc[2][3]=fmaf(q2,k3,acc[2][3]);
            acc[3][0]=fmaf(q3,k0,acc[3][0]); acc[3][1]=fmaf(q3,k1,acc[3][1]);
            acc[3][2]=fmaf(q3,k2,acc[3][2]); acc[3][3]=fmaf(q3,k3,acc[3][3]);
        }
#pragma unroll
        for (int i = 0; i < 4; i++) {
            int r = r0 + i;
#pragma unroll
            for (int jc = 0; jc < 4; jc++) {
                int cc = c0 + jc;
                float p = acc[i][jc];
                if (r == cc) sdg[r] = p;
                sA[r * 65 + cc] = (r >= cc) ? p * slp[r - cc] : 0.f;
            }
        }
    }
    __syncthreads();

    {
        int rr = (tid >> 3) * 2;
        int c0 = (tid & 7) * 8;
        float aA[2][8], aI[2][8];
#pragma unroll
        for (int i = 0; i < 2; i++)
#pragma unroll
            for (int jc = 0; jc < 8; jc++) { aA[i][jc] = 0.f; aI[i][jc] = 0.f; }
        float cs0 = 0.f, cs1 = 0.f, cq0 = 0.f, cq1 = 0.f;

        for (int s = 0; s < 64; s++) {
            float a0 = sA[rr * 65 + s];
            float a1 = sA[(rr + 1) * 65 + s];
            cs0 += a0; cs1 += a1;
            float4 v0 = *(const float4*)(sV + s * 64 + c0);
            float4 v1 = *(const float4*)(sV + s * 64 + c0 + 4);
            aA[0][0]=fmaf(a0,v0.x,aA[0][0]); aA[0][1]=fmaf(a0,v0.y,aA[0][1]);
            aA[0][2]=fmaf(a0,v0.z,aA[0][2]); aA[0][3]=fmaf(a0,v0.w,aA[0][3]);
            aA[0][4]=fmaf(a0,v1.x,aA[0][4]); aA[0][5]=fmaf(a0,v1.y,aA[0][5]);
            aA[0][6]=fmaf(a0,v1.z,aA[0][6]); aA[0][7]=fmaf(a0,v1.w,aA[0][7]);
            aA[1][0]=fmaf(a1,v0.x,aA[1][0]); aA[1][1]=fmaf(a1,v0.y,aA[1][1]);
            aA[1][2]=fmaf(a1,v0.z,aA[1][2]); aA[1][3]=fmaf(a1,v0.w,aA[1][3]);
            aA[1][4]=fmaf(a1,v1.x,aA[1][4]); aA[1][5]=fmaf(a1,v1.y,aA[1][5]);
            aA[1][6]=fmaf(a1,v1.z,aA[1][6]); aA[1][7]=fmaf(a1,v1.w,aA[1][7]);
        }
        for (int d = 0; d < 64; d++) {
            float q0 = sQ[rr * 65 + d];
            float q1 = sQ[(rr + 1) * 65 + d];
            cq0 = fmaf(q0, szp[d], cq0);
            cq1 = fmaf(q1, szp[d], cq1);
#pragma unroll
            for (int jc = 0; jc < 8; jc++) {
                float sv = sS[(c0 + jc) * 65 + d];
                aI[0][jc] = fmaf(q0, sv, aI[0][jc]);
                aI[1][jc] = fmaf(q1, sv, aI[1][jc]);
            }
        }

        float* Yg = g_Y + (size_t)(dir * NBH_ + bh) * T_ * HD_;
        float* Cg = g_C + (size_t)(dir * NBH_ + bh) * T_;
#pragma unroll
        for (int i = 0; i < 2; i++) {
            int r = rr + i;
            int pt = dir ? (T_ - 1 - (j * CH_ + r)) : (j * CH_ + r);
            float lf = slp[r + 1];
            float qk = sdg[r];
#pragma unroll
            for (int jc = 0; jc < 8; jc++) {
                int e = c0 + jc;
                Yg[(size_t)pt * HD_ + e] = aA[i][jc] + lf * aI[i][jc] - 0.5f * qk * sV[r * 64 + e];
            }
            if (c0 == 0)
                Cg[pt] = (i ? cs1 : cs0) + lf * (i ? cq1 : cq0) - 0.5f * qk;
        }
    }
}

// ------------------------- combine + split ---------------------------------
__global__ void __launch_bounds__(256) combine_kernel()
{
    int i = blockIdx.x * 256 + threadIdx.x;
    int e  = i & 63;
    int tt = (i >> 6) & (T_ - 1);
    int bh = i >> 17;
    int b  = bh >> 3;
    int h  = bh & 7;

    float yf  = g_Y[i];
    float ybk = g_Y[i + NBH_ * T_ * HD_];
    float cf  = g_C[bh * T_ + tt];
    float cbk = g_C[bh * T_ + tt + NBH_ * T_];
    float v = (yf + ybk) / fmaxf(cf + cbk, 1e-6f);
    size_t dst = ((size_t)(b * T_ + tt) * D_) + h * HD_ + e;
    __nv_bfloat16 hv = __float2bfloat16(v);
    g_ath[dst] = hv;
    g_atl[dst] = __float2bfloat16(v - __bfloat162float(hv));
}

// ------------------------- launcher ----------------------------------------
extern "C" void kernel_launch(void* const* d_in, const int* in_sizes, int n_in,
                              void* d_out, int out_size)
{
    const float* x    = (const float*)d_in[0];
    const float* Wq   = (const float*)d_in[2];
    const float* Wk   = (const float*)d_in[3];
    const float* Wv   = (const float*)d_in[4];
    const float* Wo   = (const float*)d_in[5];
    const float* bo   = (const float*)d_in[6];
    const float* g1   = (const float*)d_in[7];
    const float* b1   = (const float*)d_in[8];
    const float* g2   = (const float*)d_in[9];
    const float* b2   = (const float*)d_in[10];
    const float* W1   = (const float*)d_in[11];
    const float* bf1  = (const float*)d_in[12];
    const float* W2   = (const float*)d_in[13];
    const float* bf2  = (const float*)d_in[14];
    const float* dlog = (const float*)d_in[15];
    float* out = (float*)d_out;

#define SYM(p, s) cudaGetSymbolAddress((void**)&p, s)
    __nv_bfloat16 *xnh,*xnl,*ath,*atl,*h2h,*h2l,*f1h,*f1l;
    __nv_bfloat16 *wqkvh,*wqkvl,*woh,*wol,*w1h,*w1l,*w2h,*w2l;
    float *QKV,*x2;
    SYM(xnh,g_xnh); SYM(xnl,g_xnl); SYM(ath,g_ath); SYM(atl,g_atl);
    SYM(h2h,g_h2h); SYM(h2l,g_h2l); SYM(f1h,g_f1h); SYM(f1l,g_f1l);
    SYM(wqkvh,g_wqkvh); SYM(wqkvl,g_wqkvl);
    SYM(woh,g_woh); SYM(wol,g_wol);
    SYM(w1h,g_w1h); SYM(w1l,g_w1l); SYM(w2h,g_w2h); SYM(w2l,g_w2l);
    SYM(QKV,g_QKV); SYM(x2,g_x2);
#undef SYM

    cudaFuncSetAttribute(tc_gemm<2,512>,      cudaFuncAttributeMaxDynamicSharedMemorySize, GEMM_SMEM);
    cudaFuncSetAttribute(tc_gemm<2,2048>,     cudaFuncAttributeMaxDynamicSharedMemorySize, GEMM_SMEM);
    cudaFuncSetAttribute(tc_gemm_big<0,512>,  cudaFuncAttributeMaxDynamicSharedMemorySize, GEMM2_SMEM);
    cudaFuncSetAttribute(tc_gemm_big<3,512>,  cudaFuncAttributeMaxDynamicSharedMemorySize, GEMM2_SMEM);
    cudaFuncSetAttribute(chunk_kernel,        cudaFuncAttributeMaxDynamicSharedMemorySize, P2_SMEM_BYTES);

    dim3 blk(256);
    dim3 gD(D_ / 128, M_ / 128);        // (4, 32)
    dim3 gQKV((3*D_) / 256, M_ / 128);  // (6, 32)
    dim3 gF1(F_ / 256, M_ / 128);       // (8, 32)

    // 0) all weight splits in one launch
    split_all_kernel<<<3145728/256, blk>>>(Wq, Wk, Wv, Wo, W1, W2);
    // 1) LN1 (+split)
    ln_split_kernel<<<M_, blk>>>(x, g1, b1, xnh, xnl);
    // 2) fused Q/K/V projection (tensor cores, 128x256 tile)
    tc_gemm_big<0,512><<<gQKV, blk, GEMM2_SMEM>>>(xnh, xnl, wqkvh, wqkvl, 3*D_,
                                                  nullptr, QKV, nullptr, nullptr);
    // 3) chunked bidirectional recurrence
    scan_kernel<<<2 * NBH_ * 4, blk>>>(dlog);
    chunk_kernel<<<2 * NBH_ * NCH_, blk, P2_SMEM_BYTES>>>(dlog);
    // 4) combine (+split)
    combine_kernel<<<(NBH_ * T_ * HD_) / 256, blk>>>();
    // 5) Wo + bias + residual -> fp32 x2
    tc_gemm<2,512><<<gD, blk, GEMM_SMEM>>>(ath, atl, woh, wol, D_, bo, x, x2);
    // 6) LN2 (+split)
    ln_split_kernel<<<M_, blk>>>(x2, g2, b2, h2h, h2l);
    // 7) FFN up + GELU -> split bf16 (128x256 tile)
    tc_gemm_big<3,512><<<gF1, blk, GEMM2_SMEM>>>(h2h, h2l, w1h, w1l, F_,
                                                 bf1, nullptr, f1h, f1l);
    // 8) FFN down + bias + residual -> final output
    tc_gemm<2,2048><<<gD, blk, GEMM_SMEM>>>(f1h, f1l, w2h, w2l, D_, bf2, x2, out);
}

// round 10
// speedup vs baseline: 1.1017x; 1.1017x over previous
#include <cuda_runtime.h>
#include <cuda_bf16.h>
#include <math.h>
#include <stdint.h>

#define B_   2
#define T_   2048
#define D_   512
#define H_   8
#define HD_  64
#define F_   2048
#define M_   (B_*T_)
#define CH_  64
#define NCH_ (T_/CH_)
#define NBH_ (B_*H_)
#define QKVO (NBH_*T_*HD_)

// ------------------------- scratch globals ---------------------------------
__device__ __nv_bfloat16 g_xnh[M_*D_], g_xnl[M_*D_];
__device__ __nv_bfloat16 g_ath[M_*D_], g_atl[M_*D_];
__device__ __nv_bfloat16 g_h2h[M_*D_], g_h2l[M_*D_];
__device__ __nv_bfloat16 g_f1h[M_*F_], g_f1l[M_*F_];
__device__ __nv_bfloat16 g_wqkvh[3*D_*D_], g_wqkvl[3*D_*D_];   // Wq|Wk|Wv rows
__device__ __nv_bfloat16 g_woh[D_*D_], g_wol[D_*D_];
__device__ __nv_bfloat16 g_w1h[F_*D_], g_w1l[F_*D_];
__device__ __nv_bfloat16 g_w2h[D_*F_], g_w2l[D_*F_];
__device__ float g_QKV[3*QKVO];                                // Q|K|V [b,h,t,e]
__device__ float g_Y[2*NBH_*T_*HD_], g_C[2*NBH_*T_];
__device__ float g_x2[M_*D_];
__device__ float g_Schk[2*NBH_*NCH_*HD_*HD_];   // states ENTERING each chunk
__device__ float g_zchk[2*NBH_*NCH_*HD_];
__device__ float g_U   [2*NBH_*NCH_*HD_*HD_];   // per-chunk partial sums
__device__ float g_zU  [2*NBH_*NCH_*HD_];

// ------------------------- helpers -----------------------------------------
static __device__ __forceinline__ uint32_t stou(const void* p){
    uint32_t a;
    asm("{ .reg .u64 t; cvta.to.shared.u64 t, %1; cvt.u32.u64 %0, t; }" : "=r"(a) : "l"(p));
    return a;
}
static __device__ __forceinline__ void cp16(uint32_t dst, const void* src){
    asm volatile("cp.async.cg.shared.global [%0], [%1], 16;" :: "r"(dst), "l"(src));
}
static __device__ __forceinline__ void ldmA(uint32_t* a, uint32_t addr){
    asm volatile("ldmatrix.sync.aligned.m8n8.x4.shared.b16 {%0,%1,%2,%3}, [%4];"
        : "=r"(a[0]),"=r"(a[1]),"=r"(a[2]),"=r"(a[3]) : "r"(addr));
}
static __device__ __forceinline__ void ldmB(uint32_t* b, uint32_t addr){
    asm volatile("ldmatrix.sync.aligned.m8n8.x2.shared.b16 {%0,%1}, [%2];"
        : "=r"(b[0]),"=r"(b[1]) : "r"(addr));
}
static __device__ __forceinline__ void mma16816(float* c, const uint32_t* a, const uint32_t* b){
    asm volatile("mma.sync.aligned.m16n8k16.row.col.f32.bf16.bf16.f32 "
        "{%0,%1,%2,%3}, {%4,%5,%6,%7}, {%8,%9}, {%0,%1,%2,%3};"
        : "+f"(c[0]),"+f"(c[1]),"+f"(c[2]),"+f"(c[3])
        : "r"(a[0]),"r"(a[1]),"r"(a[2]),"r"(a[3]), "r"(b[0]),"r"(b[1]));
}

#define ROWB  144
#define ATILE 18432
#define STGB  36864
#define GEMM_SMEM (2*STGB)

// ---------------------------------------------------------------------------
// 128x128 split-bf16 GEMM (K'=3K), 2-stage (validated R8).
// MODE: 0=scatter+elu  1=scatter  2=bias+res->fp32  3=bias+gelu->split bf16
// ---------------------------------------------------------------------------
template<int MODE, int KDIM>
__global__ void __launch_bounds__(256,2) tc_gemm(
    const __nv_bfloat16* __restrict__ Ah, const __nv_bfloat16* __restrict__ Al,
    const __nv_bfloat16* __restrict__ Bh, const __nv_bfloat16* __restrict__ Bl,
    int N, const float* __restrict__ bias, const float* __restrict__ res,
    float* __restrict__ outF,
    __nv_bfloat16* __restrict__ outH, __nv_bfloat16* __restrict__ outL)
{
    extern __shared__ char dyns[];
    uint32_t sb = stou(dyns);

    int tid = threadIdx.x;
    int lane = tid & 31, w = tid >> 5;
    int warp_m = w >> 2, warp_n = w & 3;
    int m0 = blockIdx.y * 128;
    int n0 = blockIdx.x * 128;

    float acc[4][4][4];
#pragma unroll
    for (int i=0;i<4;i++)
#pragma unroll
        for (int j=0;j<4;j++)
#pragma unroll
            for (int k=0;k<4;k++) acc[i][j][k] = 0.f;

    const int NIT = 3*KDIM/64;

    auto fill = [&](int itf){
        int st = itf & 1;
        int kp = itf * 64;
        int pass = kp / KDIM;
        int koff = kp - pass*KDIM;
        const __nv_bfloat16* pA = (pass==1)? Al : Ah;
        const __nv_bfloat16* pB = (pass==2)? Bl : Bh;
        uint32_t base = sb + st*STGB;
#pragma unroll
        for (int i=0;i<8;i++){
            int q = tid + i*256;
            int isB = q >> 10;
            int r   = (q >> 3) & 127;
            int c16 = q & 7;
            const __nv_bfloat16* src =
                (isB ? (pB + (size_t)(n0+r)*KDIM) : (pA + (size_t)(m0+r)*KDIM)) + koff + c16*8;
            cp16(base + isB*ATILE + r*ROWB + c16*16, src);
        }
        asm volatile("cp.async.commit_group;" ::: "memory");
    };

    uint32_t aBase = (uint32_t)((warp_m*64 + (lane & 15))*ROWB + ((lane >> 4) << 4));
    uint32_t bBase = (uint32_t)(ATILE + (warp_n*32 + (lane & 7))*ROWB + (((lane >> 3) & 1) << 4));

    fill(0);
    for (int it=0; it<NIT; ++it){
        if (it+1 < NIT){
            fill(it+1);
            asm volatile("cp.async.wait_group 1;" ::: "memory");
        } else {
            asm volatile("cp.async.wait_group 0;" ::: "memory");
        }
        __syncthreads();
        uint32_t stg = sb + (it&1)*STGB;
#pragma unroll
        for (int kk=0; kk<64; kk+=16){
            uint32_t afrag[4][4], bfrag[4][2];
#pragma unroll
            for (int mt=0;mt<4;mt++) ldmA(afrag[mt], stg + aBase + mt*(16*ROWB) + kk*2);
#pragma unroll
            for (int nt=0;nt<4;nt++) ldmB(bfrag[nt], stg + bBase + nt*(8*ROWB) + kk*2);
#pragma unroll
            for (int mt=0;mt<4;mt++)
#pragma unroll
                for (int nt=0;nt<4;nt++) mma16816(acc[mt][nt], afrag[mt], bfrag[nt]);
        }
        __syncthreads();
    }

    int mb = m0 + warp_m*64;
    int nb = n0 + warp_n*32;
#pragma unroll
    for (int mt=0; mt<4; mt++){
#pragma unroll
        for (int half=0; half<2; half++){
            int m = mb + mt*16 + (lane>>2) + half*8;
            int bb = m >> 11, tt = m & (T_-1);
#pragma unroll
            for (int nt=0; nt<4; nt++){
                int n = nb + nt*8 + (lane&3)*2;
                float v0 = acc[mt][nt][half*2];
                float v1 = acc[mt][nt][half*2+1];
                if (MODE == 0 || MODE == 1){
                    if (MODE == 0){
                        v0 = v0>0.f ? v0+1.f : expf(v0);
                        v1 = v1>0.f ? v1+1.f : expf(v1);
                    }
                    int hh = n >> 6, ee = n & 63;
                    float* dst = outF + ((((size_t)(bb*H_ + hh))*T_ + tt)<<6) + ee;
                    float2 o; o.x=v0; o.y=v1;
                    *(float2*)dst = o;
                } else if (MODE == 2){
                    size_t idx = (size_t)m*N + n;
                    float2 rv = *(const float2*)(res + idx);
                    float2 o;
                    o.x = v0 + bias[n]   + rv.x;
                    o.y = v1 + bias[n+1] + rv.y;
                    *(float2*)(outF + idx) = o;
                } else {   // MODE 3
                    size_t idx = (size_t)m*N + n;
                    float a = v0 + bias[n];
                    float b = v1 + bias[n+1];
                    a = 0.5f*a*(1.f+erff(a*0.70710678118654752f));
                    b = 0.5f*b*(1.f+erff(b*0.70710678118654752f));
                    __nv_bfloat16 ha=__float2bfloat16(a), hb=__float2bfloat16(b);
                    float la = a-__bfloat162float(ha), lb = b-__bfloat162float(hb);
                    uint32_t hp = (uint32_t)__bfloat16_as_ushort(ha) |
                                  ((uint32_t)__bfloat16_as_ushort(hb)<<16);
                    uint32_t lp = (uint32_t)__bfloat16_as_ushort(__float2bfloat16(la)) |
                                  ((uint32_t)__bfloat16_as_ushort(__float2bfloat16(lb))<<16);
                    *(uint32_t*)(outH + idx) = hp;
                    *(uint32_t*)(outL + idx) = lp;
                }
            }
        }
    }
}

// ------------------------- batched weight split ------------------------------
__global__ void __launch_bounds__(256) split_all_kernel(
    const float* __restrict__ Wq, const float* __restrict__ Wk,
    const float* __restrict__ Wv, const float* __restrict__ Wo,
    const float* __restrict__ W1, const float* __restrict__ W2)
{
    int i = blockIdx.x * 256 + threadIdx.x;
    float v; __nv_bfloat16 *dh, *dl; int j;
    if (i < 786432){
        int which = i >> 18; j = i & 262143;
        v = (which==0 ? Wq : which==1 ? Wk : Wv)[j];
        dh = g_wqkvh + i; dl = g_wqkvl + i;
    } else if (i < 1048576){
        j = i - 786432; v = Wo[j]; dh = g_woh + j; dl = g_wol + j;
    } else if (i < 2097152){
        j = i - 1048576; v = W1[j]; dh = g_w1h + j; dl = g_w1l + j;
    } else {
        j = i - 2097152; v = W2[j]; dh = g_w2h + j; dl = g_w2l + j;
    }
    __nv_bfloat16 hh = __float2bfloat16(v);
    *dh = hh;
    *dl = __float2bfloat16(v - __bfloat162float(hh));
}

// ------------------------- LayerNorm + split --------------------------------
__global__ void __launch_bounds__(256) ln_split_kernel(
    const float* __restrict__ x, const float* __restrict__ g,
    const float* __restrict__ b, __nv_bfloat16* __restrict__ yh,
    __nv_bfloat16* __restrict__ yl)
{
    int row = blockIdx.x;
    const float* xr = x + (size_t)row * D_;
    int tid = threadIdx.x;
    float v0 = xr[tid], v1 = xr[tid + 256];
    float s  = v0 + v1, ss = v0*v0 + v1*v1;
    __shared__ float sh[16];
#pragma unroll
    for (int o = 16; o; o >>= 1) {
        s  += __shfl_xor_sync(0xffffffffu, s,  o);
        ss += __shfl_xor_sync(0xffffffffu, ss, o);
    }
    int w = tid >> 5;
    if ((tid & 31) == 0) { sh[w] = s; sh[w + 8] = ss; }
    __syncthreads();
    float S = 0.f, SS = 0.f;
#pragma unroll
    for (int i = 0; i < 8; i++) { S += sh[i]; SS += sh[8 + i]; }
    float mean = S * (1.0f / D_);
    float rstd = rsqrtf(SS * (1.0f / D_) - mean*mean + 1e-5f);
    size_t base = (size_t)row * D_;
    float o0 = (v0 - mean) * rstd * g[tid]       + b[tid];
    float o1 = (v1 - mean) * rstd * g[tid + 256] + b[tid + 256];
    __nv_bfloat16 h0 = __float2bfloat16(o0), h1 = __float2bfloat16(o1);
    yh[base + tid]       = h0;
    yh[base + tid + 256] = h1;
    yl[base + tid]       = __float2bfloat16(o0 - __bfloat162float(h0));
    yl[base + tid + 256] = __float2bfloat16(o1 - __bfloat162float(h1));
}

// ---------------------------------------------------------------------------
// Scan level 1: per-chunk partials, fully parallel.
// U_j[e][d] = sum_s lam^(C-1-s) k_s[d] v_s[e];  zU_j[d] = sum_s lam^(C-1-s) k_s[d]
// grid = 2*16*32 = 1024 blocks, 256 threads. Thread (d=tid&63, c=tid>>6)
// accumulates e in [c*16, c*16+16).
// ---------------------------------------------------------------------------
__global__ void __launch_bounds__(256) usum_kernel(const float* __restrict__ dlogit)
{
    int bx  = blockIdx.x;
    int j   = bx & 31;
    int bh  = (bx >> 5) & 15;
    int dir = bx >> 9;
    int h   = bh & 7;
    float lam = 1.f / (1.f + expf(-dlogit[h]));

    __shared__ float sK[CH_ * HD_];
    __shared__ float sV[CH_ * HD_];
    __shared__ float w [CH_];

    int tid = threadIdx.x;
    if (tid < CH_) w[tid] = powf(lam, (float)(CH_ - 1 - tid));

    int lrow = tid >> 2;
    int lseg = (tid & 3) * 16;
    int pt = dir ? (T_ - 1 - (j * CH_ + lrow)) : (j * CH_ + lrow);
    const float* Kg = g_QKV + QKVO     + (size_t)bh * T_ * HD_;
    const float* Vg = g_QKV + 2*QKVO   + (size_t)bh * T_ * HD_;
    {
        const float4* kr = (const float4*)(Kg + (size_t)pt * HD_ + lseg);
        const float4* vr = (const float4*)(Vg + (size_t)pt * HD_ + lseg);
        float4* sk = (float4*)(sK + lrow * HD_ + lseg);
        float4* sv = (float4*)(sV + lrow * HD_ + lseg);
        sk[0]=kr[0]; sk[1]=kr[1]; sk[2]=kr[2]; sk[3]=kr[3];
        sv[0]=vr[0]; sv[1]=vr[1]; sv[2]=vr[2]; sv[3]=vr[3];
    }
    __syncthreads();

    int d = tid & 63, c = tid >> 6;
    int e0 = c * 16;
    float acc[16];
#pragma unroll
    for (int i = 0; i < 16; i++) acc[i] = 0.f;
    float zacc = 0.f;

#pragma unroll 4
    for (int s = 0; s < CH_; s++){
        float kk = sK[s * HD_ + d] * w[s];
        zacc += kk;
        const float4* vv = (const float4*)(sV + s * HD_ + e0);
        float4 a0 = vv[0], a1 = vv[1], a2 = vv[2], a3 = vv[3];
        acc[0] = fmaf(kk, a0.x, acc[0]);  acc[1] = fmaf(kk, a0.y, acc[1]);
        acc[2] = fmaf(kk, a0.z, acc[2]);  acc[3] = fmaf(kk, a0.w, acc[3]);
        acc[4] = fmaf(kk, a1.x, acc[4]);  acc[5] = fmaf(kk, a1.y, acc[5]);
        acc[6] = fmaf(kk, a1.z, acc[6]);  acc[7] = fmaf(kk, a1.w, acc[7]);
        acc[8] = fmaf(kk, a2.x, acc[8]);  acc[9] = fmaf(kk, a2.y, acc[9]);
        acc[10]= fmaf(kk, a2.z, acc[10]); acc[11]= fmaf(kk, a2.w, acc[11]);
        acc[12]= fmaf(kk, a3.x, acc[12]); acc[13]= fmaf(kk, a3.y, acc[13]);
        acc[14]= fmaf(kk, a3.z, acc[14]); acc[15]= fmaf(kk, a3.w, acc[15]);
    }

    float* U = g_U + (size_t)((dir * NBH_ + bh) * NCH_ + j) * (HD_ * HD_);
#pragma unroll
    for (int i = 0; i < 16; i++) U[(e0 + i) * 64 + d] = acc[i];
    if (c == 0)
        g_zU[(size_t)((dir * NBH_ + bh) * NCH_ + j) * HD_ + d] = zacc;
}

// ---------------------------------------------------------------------------
// Scan level 2: tiny sequential sweep over 32 chunks, parallel over elements.
// grid = 2*16*16 = 512 blocks, 256 threads; element = seg*256 + tid.
// ---------------------------------------------------------------------------
__global__ void __launch_bounds__(256) sweep_kernel(const float* __restrict__ dlogit)
{
    int bx  = blockIdx.x;
    int seg = bx & 15;
    int bh  = (bx >> 4) & 15;
    int dir = bx >> 8;
    int h   = bh & 7;
    float lam  = 1.f / (1.f + expf(-dlogit[h]));
    float lamC = powf(lam, (float)CH_);

    int el = seg * 256 + threadIdx.x;                 // 0..4095
    size_t base = (size_t)((dir * NBH_ + bh) * NCH_) * (HD_ * HD_);
    float S = 0.f;
#pragma unroll
    for (int jj = 0; jj < NCH_; jj++){
        size_t o = base + (size_t)jj * (HD_ * HD_) + el;
        float u = g_U[o];
        g_Schk[o] = S;
        S = fmaf(lamC, S, u);
    }
    if (seg == 0 && threadIdx.x < HD_){
        int d = threadIdx.x;
        size_t zb = (size_t)((dir * NBH_ + bh) * NCH_) * HD_;
        float z = 0.f;
#pragma unroll
        for (int jj = 0; jj < NCH_; jj++){
            float zu = g_zU[zb + jj * HD_ + d];
            g_zchk[zb + jj * HD_ + d] = z;
            z = fmaf(lamC, z, zu);
        }
    }
}

// ------------------------- chunk kernel (validated) --------------------------
#define SOFF_Q   0
#define SOFF_K   4160
#define SOFF_A   8320
#define SOFF_S   12480
#define SOFF_V   16640
#define SOFF_ZP  20736
#define SOFF_DG  20800
#define SOFF_LP  20864
#define P2_SMEM_BYTES ((20864 + 80) * 4)

__global__ void __launch_bounds__(256) chunk_kernel(const float* __restrict__ dlogit)
{
    extern __shared__ float sm[];
    float* sQ  = sm + SOFF_Q;
    float* sK  = sm + SOFF_K;
    float* sA  = sm + SOFF_A;
    float* sS  = sm + SOFF_S;
    float* sV  = sm + SOFF_V;
    float* szp = sm + SOFF_ZP;
    float* sdg = sm + SOFF_DG;
    float* slp = sm + SOFF_LP;

    int bx  = blockIdx.x;
    int j   = bx & 31;
    int bh  = (bx >> 5) & 15;
    int dir = bx >> 9;
    int h   = bh & 7;
    float lam = 1.f / (1.f + expf(-dlogit[h]));

    int tid = threadIdx.x;
    if (tid <= CH_) slp[tid] = powf(lam, (float)tid);

    const float* Qg  = g_QKV            + (size_t)bh * T_ * HD_;
    const float* Kg  = g_QKV + QKVO     + (size_t)bh * T_ * HD_;
    const float* Vg  = g_QKV + 2*QKVO   + (size_t)bh * T_ * HD_;
    const float* Sin = g_Schk + (size_t)((dir * NBH_ + bh) * NCH_ + j) * (HD_ * HD_);
    const float* zin = g_zchk + (size_t)((dir * NBH_ + bh) * NCH_ + j) * HD_;

    int lrow = tid >> 2;
    int lseg = (tid & 3) * 16;
    int pt0 = dir ? (T_ - 1 - (j * CH_ + lrow)) : (j * CH_ + lrow);

#pragma unroll 4
    for (int i = 0; i < 16; i++) {
        sQ[lrow * 65 + lseg + i] = Qg[(size_t)pt0 * HD_ + lseg + i];
        sK[lrow * 65 + lseg + i] = Kg[(size_t)pt0 * HD_ + lseg + i];
    }
    {
        float4* svr = (float4*)(sV + lrow * 64 + lseg);
        const float4* vr = (const float4*)(Vg + (size_t)pt0 * HD_ + lseg);
        svr[0]=vr[0]; svr[1]=vr[1]; svr[2]=vr[2]; svr[3]=vr[3];
    }
#pragma unroll 4
    for (int i = 0; i < 16; i++) {
        int idx = tid * 16 + i;
        int e = idx >> 6, dd = idx & 63;
        sS[e * 65 + dd] = Sin[idx];
    }
    if (tid < 64) szp[tid] = zin[tid];
    __syncthreads();

    {
        int ty = tid >> 4, tx = tid & 15;
        int r0 = ty * 4, c0 = tx * 4;
        float acc[4][4];
#pragma unroll
        for (int i = 0; i < 4; i++)
#pragma unroll
            for (int jc = 0; jc < 4; jc++) acc[i][jc] = 0.f;

        for (int d = 0; d < 64; d++) {
            float q0 = sQ[(r0+0)*65+d], q1 = sQ[(r0+1)*65+d];
            float q2 = sQ[(r0+2)*65+d], q3 = sQ[(r0+3)*65+d];
            float k0 = sK[(c0+0)*65+d], k1 = sK[(c0+1)*65+d];
            float k2 = sK[(c0+2)*65+d], k3 = sK[(c0+3)*65+d];
            acc[0][0]=fmaf(q0,k0,acc[0][0]); acc[0][1]=fmaf(q0,k1,acc[0][1]);
            acc[0][2]=fmaf(q0,k2,acc[0][2]); acc[0][3]=fmaf(q0,k3,acc[0][3]);
            acc[1][0]=fmaf(q1,k0,acc[1][0]); acc[1][1]=fmaf(q1,k1,acc[1][1]);
            acc[1][2]=fmaf(q1,k2,acc[1][2]); acc[1][3]=fmaf(q1,k3,acc[1][3]);
            acc[2][0]=fmaf(q2,k0,acc[2][0]); acc[2][1]=fmaf(q2,k1,acc[2][1]);
            acc[2][2]=fmaf(q2,k2,acc[2][2]); acc[2][3]=fmaf(q2,k3,acc[2][3]);
            acc[3][0]=fmaf(q3,k0,acc[3][0]); acc[3][1]=fmaf(q3,k1,acc[3][1]);
            acc[3][2]=fmaf(q3,k2,acc[3][2]); acc[3][3]=fmaf(q3,k3,acc[3][3]);
        }
#pragma unroll
        for (int i = 0; i < 4; i++) {
            int r = r0 + i;
#pragma unroll
            for (int jc = 0; jc < 4; jc++) {
                int cc = c0 + jc;
                float p = acc[i][jc];
                if (r == cc) sdg[r] = p;
                sA[r * 65 + cc] = (r >= cc) ? p * slp[r - cc] : 0.f;
            }
        }
    }
    __syncthreads();

    {
        int rr = (tid >> 3) * 2;
        int c0 = (tid & 7) * 8;
        float aA[2][8], aI[2][8];
#pragma unroll
        for (int i = 0; i < 2; i++)
#pragma unroll
            for (int jc = 0; jc < 8; jc++) { aA[i][jc] = 0.f; aI[i][jc] = 0.f; }
        float cs0 = 0.f, cs1 = 0.f, cq0 = 0.f, cq1 = 0.f;

        for (int s = 0; s < 64; s++) {
            float a0 = sA[rr * 65 + s];
            float a1 = sA[(rr + 1) * 65 + s];
            cs0 += a0; cs1 += a1;
            float4 v0 = *(const float4*)(sV + s * 64 + c0);
            float4 v1 = *(const float4*)(sV + s * 64 + c0 + 4);
            aA[0][0]=fmaf(a0,v0.x,aA[0][0]); aA[0][1]=fmaf(a0,v0.y,aA[0][1]);
            aA[0][2]=fmaf(a0,v0.z,aA[0][2]); aA[0][3]=fmaf(a0,v0.w,aA[0][3]);
            aA[0][4]=fmaf(a0,v1.x,aA[0][4]); aA[0][5]=fmaf(a0,v1.y,aA[0][5]);
            aA[0][6]=fmaf(a0,v1.z,aA[0][6]); aA[0][7]=fmaf(a0,v1.w,aA[0][7]);
            aA[1][0]=fmaf(a1,v0.x,aA[1][0]); aA[1][1]=fmaf(a1,v0.y,aA[1][1]);
            aA[1][2]=fmaf(a1,v0.z,aA[1][2]); aA[1][3]=fmaf(a1,v0.w,aA[1][3]);
            aA[1][4]=fmaf(a1,v1.x,aA[1][4]); aA[1][5]=fmaf(a1,v1.y,aA[1][5]);
            aA[1][6]=fmaf(a1,v1.z,aA[1][6]); aA[1][7]=fmaf(a1,v1.w,aA[1][7]);
        }
        for (int d = 0; d < 64; d++) {
            float q0 = sQ[rr * 65 + d];
            float q1 = sQ[(rr + 1) * 65 + d];
            cq0 = fmaf(q0, szp[d], cq0);
            cq1 = fmaf(q1, szp[d], cq1);
#pragma unroll
            for (int jc = 0; jc < 8; jc++) {
                float sv = sS[(c0 + jc) * 65 + d];
                aI[0][jc] = fmaf(q0, sv, aI[0][jc]);
                aI[1][jc] = fmaf(q1, sv, aI[1][jc]);
            }
        }

        float* Yg = g_Y + (size_t)(dir * NBH_ + bh) * T_ * HD_;
        float* Cg = g_C + (size_t)(dir * NBH_ + bh) * T_;
#pragma unroll
        for (int i = 0; i < 2; i++) {
            int r = rr + i;
            int pt = dir ? (T_ - 1 - (j * CH_ + r)) : (j * CH_ + r);
            float lf = slp[r + 1];
            float qk = sdg[r];
#pragma unroll
            for (int jc = 0; jc < 8; jc++) {
                int e = c0 + jc;
                Yg[(size_t)pt * HD_ + e] = aA[i][jc] + lf * aI[i][jc] - 0.5f * qk * sV[r * 64 + e];
            }
            if (c0 == 0)
                Cg[pt] = (i ? cs1 : cs0) + lf * (i ? cq1 : cq0) - 0.5f * qk;
        }
    }
}

// ------------------------- combine + split ---------------------------------
__global__ void __launch_bounds__(256) combine_kernel()
{
    int i = blockIdx.x * 256 + threadIdx.x;
    int e  = i & 63;
    int tt = (i >> 6) & (T_ - 1);
    int bh = i >> 17;
    int b  = bh >> 3;
    int h  = bh & 7;

    float yf  = g_Y[i];
    float ybk = g_Y[i + NBH_ * T_ * HD_];
    float cf  = g_C[bh * T_ + tt];
    float cbk = g_C[bh * T_ + tt + NBH_ * T_];
    float v = (yf + ybk) / fmaxf(cf + cbk, 1e-6f);
    size_t dst = ((size_t)(b * T_ + tt) * D_) + h * HD_ + e;
    __nv_bfloat16 hv = __float2bfloat16(v);
    g_ath[dst] = hv;
    g_atl[dst] = __float2bfloat16(v - __bfloat162float(hv));
}

// ------------------------- launcher ----------------------------------------
extern "C" void kernel_launch(void* const* d_in, const int* in_sizes, int n_in,
                              void* d_out, int out_size)
{
    const float* x    = (const float*)d_in[0];
    const float* Wq   = (const float*)d_in[2];
    const float* Wk   = (const float*)d_in[3];
    const float* Wv   = (const float*)d_in[4];
    const float* Wo   = (const float*)d_in[5];
    const float* bo   = (const float*)d_in[6];
    const float* g1   = (const float*)d_in[7];
    const float* b1   = (const float*)d_in[8];
    const float* g2   = (const float*)d_in[9];
    const float* b2   = (const float*)d_in[10];
    const float* W1   = (const float*)d_in[11];
    const float* bf1  = (const float*)d_in[12];
    const float* W2   = (const float*)d_in[13];
    const float* bf2  = (const float*)d_in[14];
    const float* dlog = (const float*)d_in[15];
    float* out = (float*)d_out;

#define SYM(p, s) cudaGetSymbolAddress((void**)&p, s)
    __nv_bfloat16 *xnh,*xnl,*ath,*atl,*h2h,*h2l,*f1h,*f1l;
    __nv_bfloat16 *wqkvh,*wqkvl,*woh,*wol,*w1h,*w1l,*w2h,*w2l;
    float *QKV,*x2;
    SYM(xnh,g_xnh); SYM(xnl,g_xnl); SYM(ath,g_ath); SYM(atl,g_atl);
    SYM(h2h,g_h2h); SYM(h2l,g_h2l); SYM(f1h,g_f1h); SYM(f1l,g_f1l);
    SYM(wqkvh,g_wqkvh); SYM(wqkvl,g_wqkvl);
    SYM(woh,g_woh); SYM(wol,g_wol);
    SYM(w1h,g_w1h); SYM(w1l,g_w1l); SYM(w2h,g_w2h); SYM(w2l,g_w2l);
    SYM(QKV,g_QKV); SYM(x2,g_x2);
#undef SYM

    cudaFuncSetAttribute(tc_gemm<0,512>,  cudaFuncAttributeMaxDynamicSharedMemorySize, GEMM_SMEM);
    cudaFuncSetAttribute(tc_gemm<1,512>,  cudaFuncAttributeMaxDynamicSharedMemorySize, GEMM_SMEM);
    cudaFuncSetAttribute(tc_gemm<2,512>,  cudaFuncAttributeMaxDynamicSharedMemorySize, GEMM_SMEM);
    cudaFuncSetAttribute(tc_gemm<3,512>,  cudaFuncAttributeMaxDynamicSharedMemorySize, GEMM_SMEM);
    cudaFuncSetAttribute(tc_gemm<2,2048>, cudaFuncAttributeMaxDynamicSharedMemorySize, GEMM_SMEM);
    cudaFuncSetAttribute(chunk_kernel,    cudaFuncAttributeMaxDynamicSharedMemorySize, P2_SMEM_BYTES);

    dim3 blk(256);
    dim3 gD(D_ / 128, M_ / 128);   // (4, 32)
    dim3 gF(F_ / 128, M_ / 128);   // (16, 32)

    // 0) all weight splits, one launch
    split_all_kernel<<<3145728/256, blk>>>(Wq, Wk, Wv, Wo, W1, W2);
    // 1) LN1 (+split)
    ln_split_kernel<<<M_, blk>>>(x, g1, b1, xnh, xnl);
    // 2) Q/K/V projections (R8-proven 128x128)
    tc_gemm<0,512><<<gD, blk, GEMM_SMEM>>>(xnh, xnl, wqkvh,            wqkvl,            D_, nullptr, nullptr, QKV,          nullptr, nullptr);
    tc_gemm<0,512><<<gD, blk, GEMM_SMEM>>>(xnh, xnl, wqkvh + D_*D_,    wqkvl + D_*D_,    D_, nullptr, nullptr, QKV +   QKVO, nullptr, nullptr);
    tc_gemm<1,512><<<gD, blk, GEMM_SMEM>>>(xnh, xnl, wqkvh + 2*D_*D_,  wqkvl + 2*D_*D_,  D_, nullptr, nullptr, QKV + 2*QKVO, nullptr, nullptr);
    // 3) two-level scan + per-chunk outputs
    usum_kernel<<<2 * NBH_ * NCH_, blk>>>(dlog);    // 1024 blocks
    sweep_kernel<<<2 * NBH_ * 16, blk>>>(dlog);     // 512 blocks
    chunk_kernel<<<2 * NBH_ * NCH_, blk, P2_SMEM_BYTES>>>(dlog);
    // 4) combine (+split)
    combine_kernel<<<(NBH_ * T_ * HD_) / 256, blk>>>();
    // 5) Wo + bias + residual -> fp32 x2
    tc_gemm<2,512><<<gD, blk, GEMM_SMEM>>>(ath, atl, woh, wol, D_, bo, x, x2, nullptr, nullptr);
    // 6) LN2 (+split)
    ln_split_kernel<<<M_, blk>>>(x2, g2, b2, h2h, h2l);
    // 7) FFN up + GELU -> split bf16
    tc_gemm<3,512><<<gF, blk, GEMM_SMEM>>>(h2h, h2l, w1h, w1l, F_, bf1, nullptr, nullptr, f1h, f1l);
    // 8) FFN down + bias + residual -> final output
    tc_gemm<2,2048><<<gD, blk, GEMM_SMEM>>>(f1h, f1l, w2h, w2l, D_, bf2, x2, out, nullptr, nullptr);
}

// round 11
// speedup vs baseline: 1.1214x; 1.0178x over previous
#include <cuda_runtime.h>
#include <cuda_bf16.h>
#include <math.h>
#include <stdint.h>

#define B_   2
#define T_   2048
#define D_   512
#define H_   8
#define HD_  64
#define F_   2048
#define M_   (B_*T_)
#define CH_  64
#define NCH_ (T_/CH_)
#define NBH_ (B_*H_)
#define QKVO (NBH_*T_*HD_)

// ------------------------- scratch globals ---------------------------------
__device__ __nv_bfloat16 g_xnh[M_*D_], g_xnl[M_*D_];
__device__ __nv_bfloat16 g_ath[M_*D_], g_atl[M_*D_];
__device__ __nv_bfloat16 g_h2h[M_*D_], g_h2l[M_*D_];
__device__ __nv_bfloat16 g_f1h[M_*F_], g_f1l[M_*F_];
__device__ __nv_bfloat16 g_wqkvh[3*D_*D_], g_wqkvl[3*D_*D_];   // Wq|Wk|Wv rows
__device__ __nv_bfloat16 g_woh[D_*D_], g_wol[D_*D_];
__device__ __nv_bfloat16 g_w1h[F_*D_], g_w1l[F_*D_];
__device__ __nv_bfloat16 g_w2h[D_*F_], g_w2l[D_*F_];
__device__ float g_QKV[3*QKVO];                                // Q|K|V [b,h,t,e]
__device__ float g_Y[2*NBH_*T_*HD_], g_C[2*NBH_*T_];
__device__ float g_x2[M_*D_];
__device__ float g_Schk[2*NBH_*NCH_*HD_*HD_];
__device__ float g_zchk[2*NBH_*NCH_*HD_];
__device__ float g_U   [2*NBH_*NCH_*HD_*HD_];
__device__ float g_zU  [2*NBH_*NCH_*HD_];

// ------------------------- helpers -----------------------------------------
static __device__ __forceinline__ uint32_t stou(const void* p){
    uint32_t a;
    asm("{ .reg .u64 t; cvta.to.shared.u64 t, %1; cvt.u32.u64 %0, t; }" : "=r"(a) : "l"(p));
    return a;
}
static __device__ __forceinline__ void cp16(uint32_t dst, const void* src){
    asm volatile("cp.async.cg.shared.global [%0], [%1], 16;" :: "r"(dst), "l"(src));
}
static __device__ __forceinline__ void ldmA(uint32_t* a, uint32_t addr){
    asm volatile("ldmatrix.sync.aligned.m8n8.x4.shared.b16 {%0,%1,%2,%3}, [%4];"
        : "=r"(a[0]),"=r"(a[1]),"=r"(a[2]),"=r"(a[3]) : "r"(addr));
}
static __device__ __forceinline__ void ldmB(uint32_t* b, uint32_t addr){
    asm volatile("ldmatrix.sync.aligned.m8n8.x2.shared.b16 {%0,%1}, [%2];"
        : "=r"(b[0]),"=r"(b[1]) : "r"(addr));
}
static __device__ __forceinline__ void mma16816(float* c, const uint32_t* a, const uint32_t* b){
    asm volatile("mma.sync.aligned.m16n8k16.row.col.f32.bf16.bf16.f32 "
        "{%0,%1,%2,%3}, {%4,%5,%6,%7}, {%8,%9}, {%0,%1,%2,%3};"
        : "+f"(c[0]),"+f"(c[1]),"+f"(c[2]),"+f"(c[3])
        : "r"(a[0]),"r"(a[1]),"r"(a[2]),"r"(a[3]), "r"(b[0]),"r"(b[1]));
}

#define ROWB  144
#define ATILE 18432
#define STGB  36864
#define GEMM_SMEM (2*STGB)
// 64-row-tile variant
#define BOFF64  9216
#define STGB64  27648
#define GEMM64_SMEM (2*STGB64)

// ---------------------------------------------------------------------------
// 128x128 split-bf16 GEMM (K'=3K), 2-stage (validated R8).
// MODE: 3=bias+gelu->split bf16   4=fused QKV scatter (elu for n<1024)
// ---------------------------------------------------------------------------
template<int MODE, int KDIM>
__global__ void __launch_bounds__(256,2) tc_gemm(
    const __nv_bfloat16* __restrict__ Ah, const __nv_bfloat16* __restrict__ Al,
    const __nv_bfloat16* __restrict__ Bh, const __nv_bfloat16* __restrict__ Bl,
    int N, const float* __restrict__ bias,
    float* __restrict__ outF,
    __nv_bfloat16* __restrict__ outH, __nv_bfloat16* __restrict__ outL)
{
    extern __shared__ char dyns[];
    uint32_t sb = stou(dyns);

    int tid = threadIdx.x;
    int lane = tid & 31, w = tid >> 5;
    int warp_m = w >> 2, warp_n = w & 3;
    int m0 = blockIdx.y * 128;
    int n0 = blockIdx.x * 128;

    float acc[4][4][4];
#pragma unroll
    for (int i=0;i<4;i++)
#pragma unroll
        for (int j=0;j<4;j++)
#pragma unroll
            for (int k=0;k<4;k++) acc[i][j][k] = 0.f;

    const int NIT = 3*KDIM/64;

    auto fill = [&](int itf){
        int st = itf & 1;
        int kp = itf * 64;
        int pass = kp / KDIM;
        int koff = kp - pass*KDIM;
        const __nv_bfloat16* pA = (pass==1)? Al : Ah;
        const __nv_bfloat16* pB = (pass==2)? Bl : Bh;
        uint32_t base = sb + st*STGB;
#pragma unroll
        for (int i=0;i<8;i++){
            int q = tid + i*256;
            int isB = q >> 10;
            int r   = (q >> 3) & 127;
            int c16 = q & 7;
            const __nv_bfloat16* src =
                (isB ? (pB + (size_t)(n0+r)*KDIM) : (pA + (size_t)(m0+r)*KDIM)) + koff + c16*8;
            cp16(base + isB*ATILE + r*ROWB + c16*16, src);
        }
        asm volatile("cp.async.commit_group;" ::: "memory");
    };

    uint32_t aBase = (uint32_t)((warp_m*64 + (lane & 15))*ROWB + ((lane >> 4) << 4));
    uint32_t bBase = (uint32_t)(ATILE + (warp_n*32 + (lane & 7))*ROWB + (((lane >> 3) & 1) << 4));

    fill(0);
    for (int it=0; it<NIT; ++it){
        if (it+1 < NIT){
            fill(it+1);
            asm volatile("cp.async.wait_group 1;" ::: "memory");
        } else {
            asm volatile("cp.async.wait_group 0;" ::: "memory");
        }
        __syncthreads();
        uint32_t stg = sb + (it&1)*STGB;
#pragma unroll
        for (int kk=0; kk<64; kk+=16){
            uint32_t afrag[4][4], bfrag[4][2];
#pragma unroll
            for (int mt=0;mt<4;mt++) ldmA(afrag[mt], stg + aBase + mt*(16*ROWB) + kk*2);
#pragma unroll
            for (int nt=0;nt<4;nt++) ldmB(bfrag[nt], stg + bBase + nt*(8*ROWB) + kk*2);
#pragma unroll
            for (int mt=0;mt<4;mt++)
#pragma unroll
                for (int nt=0;nt<4;nt++) mma16816(acc[mt][nt], afrag[mt], bfrag[nt]);
        }
        __syncthreads();
    }

    int mb = m0 + warp_m*64;
    int nb = n0 + warp_n*32;
#pragma unroll
    for (int mt=0; mt<4; mt++){
#pragma unroll
        for (int half=0; half<2; half++){
            int m = mb + mt*16 + (lane>>2) + half*8;
            int bb = m >> 11, tt = m & (T_-1);
#pragma unroll
            for (int nt=0; nt<4; nt++){
                int n = nb + nt*8 + (lane&3)*2;
                float v0 = acc[mt][nt][half*2];
                float v1 = acc[mt][nt][half*2+1];
                if (MODE == 4){
                    int mat = n >> 9;              // 0=Q 1=K 2=V
                    if (mat < 2){
                        v0 = v0>0.f ? v0+1.f : expf(v0);
                        v1 = v1>0.f ? v1+1.f : expf(v1);
                    }
                    int hh = (n >> 6) & 7, ee = n & 63;
                    float* dst = outF + (size_t)mat*QKVO
                               + ((((size_t)(bb*H_ + hh))*T_ + tt)<<6) + ee;
                    float2 o; o.x=v0; o.y=v1;
                    *(float2*)dst = o;
                } else {   // MODE 3: bias + exact GELU -> split bf16
                    size_t idx = (size_t)m*N + n;
                    float a = v0 + bias[n];
                    float b = v1 + bias[n+1];
                    a = 0.5f*a*(1.f+erff(a*0.70710678118654752f));
                    b = 0.5f*b*(1.f+erff(b*0.70710678118654752f));
                    __nv_bfloat16 ha=__float2bfloat16(a), hb=__float2bfloat16(b);
                    float la = a-__bfloat162float(ha), lb = b-__bfloat162float(hb);
                    uint32_t hp = (uint32_t)__bfloat16_as_ushort(ha) |
                                  ((uint32_t)__bfloat16_as_ushort(hb)<<16);
                    uint32_t lp = (uint32_t)__bfloat16_as_ushort(__float2bfloat16(la)) |
                                  ((uint32_t)__bfloat16_as_ushort(__float2bfloat16(lb))<<16);
                    *(uint32_t*)(outH + idx) = hp;
                    *(uint32_t*)(outL + idx) = lp;
                }
            }
        }
    }
}

// ---------------------------------------------------------------------------
// 64x128 split-bf16 GEMM, 2-stage, 3 CTAs/SM. MODE 2: bias+res -> fp32.
// Warp tile 32x32 (8 warps as 2x4).
// ---------------------------------------------------------------------------
template<int KDIM>
__global__ void __launch_bounds__(256,3) tc_gemm64(
    const __nv_bfloat16* __restrict__ Ah, const __nv_bfloat16* __restrict__ Al,
    const __nv_bfloat16* __restrict__ Bh, const __nv_bfloat16* __restrict__ Bl,
    int N, const float* __restrict__ bias, const float* __restrict__ res,
    float* __restrict__ outF)
{
    extern __shared__ char dyns[];
    uint32_t sb = stou(dyns);

    int tid = threadIdx.x;
    int lane = tid & 31, w = tid >> 5;
    int warp_m = w >> 2, warp_n = w & 3;
    int m0 = blockIdx.y * 64;
    int n0 = blockIdx.x * 128;

    float acc[2][4][4];
#pragma unroll
    for (int i=0;i<2;i++)
#pragma unroll
        for (int j=0;j<4;j++)
#pragma unroll
            for (int k=0;k<4;k++) acc[i][j][k] = 0.f;

    const int NIT = 3*KDIM/64;

    auto fill = [&](int itf){
        int st = itf & 1;
        int kp = itf * 64;
        int pass = kp / KDIM;
        int koff = kp - pass*KDIM;
        const __nv_bfloat16* pA = (pass==1)? Al : Ah;
        const __nv_bfloat16* pB = (pass==2)? Bl : Bh;
        uint32_t base = sb + st*STGB64;
#pragma unroll
        for (int i=0;i<6;i++){
            int q = tid + i*256;              // 0..1535
            if (q < 512){
                int r = q >> 3, c16 = q & 7;
                cp16(base + r*ROWB + c16*16,
                     pA + (size_t)(m0+r)*KDIM + koff + c16*8);
            } else {
                int q2 = q - 512;
                int r = q2 >> 3, c16 = q2 & 7;
                cp16(base + BOFF64 + r*ROWB + c16*16,
                     pB + (size_t)(n0+r)*KDIM + koff + c16*8);
            }
        }
        asm volatile("cp.async.commit_group;" ::: "memory");
    };

    uint32_t aBase = (uint32_t)((warp_m*32 + (lane & 15))*ROWB + ((lane >> 4) << 4));
    uint32_t bBase = (uint32_t)(BOFF64 + (warp_n*32 + (lane & 7))*ROWB + (((lane >> 3) & 1) << 4));

    fill(0);
    for (int it=0; it<NIT; ++it){
        if (it+1 < NIT){
            fill(it+1);
            asm volatile("cp.async.wait_group 1;" ::: "memory");
        } else {
            asm volatile("cp.async.wait_group 0;" ::: "memory");
        }
        __syncthreads();
        uint32_t stg = sb + (it&1)*STGB64;
#pragma unroll
        for (int kk=0; kk<64; kk+=16){
            uint32_t afrag[2][4], bfrag[4][2];
#pragma unroll
            for (int mt=0;mt<2;mt++) ldmA(afrag[mt], stg + aBase + mt*(16*ROWB) + kk*2);
#pragma unroll
            for (int nt=0;nt<4;nt++) ldmB(bfrag[nt], stg + bBase + nt*(8*ROWB) + kk*2);
#pragma unroll
            for (int mt=0;mt<2;mt++)
#pragma unroll
                for (int nt=0;nt<4;nt++) mma16816(acc[mt][nt], afrag[mt], bfrag[nt]);
        }
        __syncthreads();
    }

    int mb = m0 + warp_m*32;
    int nb = n0 + warp_n*32;
#pragma unroll
    for (int mt=0; mt<2; mt++){
#pragma unroll
        for (int half=0; half<2; half++){
            int m = mb + mt*16 + (lane>>2) + half*8;
#pragma unroll
            for (int nt=0; nt<4; nt++){
                int n = nb + nt*8 + (lane&3)*2;
                float v0 = acc[mt][nt][half*2];
                float v1 = acc[mt][nt][half*2+1];
                size_t idx = (size_t)m*N + n;
                float2 rv = *(const float2*)(res + idx);
                float2 o;
                o.x = v0 + bias[n]   + rv.x;
                o.y = v1 + bias[n+1] + rv.y;
                *(float2*)(outF + idx) = o;
            }
        }
    }
}

// ------------------------- batched weight split ------------------------------
__global__ void __launch_bounds__(256) split_all_kernel(
    const float* __restrict__ Wq, const float* __restrict__ Wk,
    const float* __restrict__ Wv, const float* __restrict__ Wo,
    const float* __restrict__ W1, const float* __restrict__ W2)
{
    int i = blockIdx.x * 256 + threadIdx.x;
    float v; __nv_bfloat16 *dh, *dl; int j;
    if (i < 786432){
        int which = i >> 18; j = i & 262143;
        v = (which==0 ? Wq : which==1 ? Wk : Wv)[j];
        dh = g_wqkvh + i; dl = g_wqkvl + i;
    } else if (i < 1048576){
        j = i - 786432; v = Wo[j]; dh = g_woh + j; dl = g_wol + j;
    } else if (i < 2097152){
        j = i - 1048576; v = W1[j]; dh = g_w1h + j; dl = g_w1l + j;
    } else {
        j = i - 2097152; v = W2[j]; dh = g_w2h + j; dl = g_w2l + j;
    }
    __nv_bfloat16 hh = __float2bfloat16(v);
    *dh = hh;
    *dl = __float2bfloat16(v - __bfloat162float(hh));
}

// ------------------------- LayerNorm + split --------------------------------
__global__ void __launch_bounds__(256) ln_split_kernel(
    const float* __restrict__ x, const float* __restrict__ g,
    const float* __restrict__ b, __nv_bfloat16* __restrict__ yh,
    __nv_bfloat16* __restrict__ yl)
{
    int row = blockIdx.x;
    const float* xr = x + (size_t)row * D_;
    int tid = threadIdx.x;
    float v0 = xr[tid], v1 = xr[tid + 256];
    float s  = v0 + v1, ss = v0*v0 + v1*v1;
    __shared__ float sh[16];
#pragma unroll
    for (int o = 16; o; o >>= 1) {
        s  += __shfl_xor_sync(0xffffffffu, s,  o);
        ss += __shfl_xor_sync(0xffffffffu, ss, o);
    }
    int w = tid >> 5;
    if ((tid & 31) == 0) { sh[w] = s; sh[w + 8] = ss; }
    __syncthreads();
    float S = 0.f, SS = 0.f;
#pragma unroll
    for (int i = 0; i < 8; i++) { S += sh[i]; SS += sh[8 + i]; }
    float mean = S * (1.0f / D_);
    float rstd = rsqrtf(SS * (1.0f / D_) - mean*mean + 1e-5f);
    size_t base = (size_t)row * D_;
    float o0 = (v0 - mean) * rstd * g[tid]       + b[tid];
    float o1 = (v1 - mean) * rstd * g[tid + 256] + b[tid + 256];
    __nv_bfloat16 h0 = __float2bfloat16(o0), h1 = __float2bfloat16(o1);
    yh[base + tid]       = h0;
    yh[base + tid + 256] = h1;
    yl[base + tid]       = __float2bfloat16(o0 - __bfloat162float(h0));
    yl[base + tid + 256] = __float2bfloat16(o1 - __bfloat162float(h1));
}

// ---------------------------------------------------------------------------
// Scan level 1: per-chunk partials (validated R10)
// ---------------------------------------------------------------------------
__global__ void __launch_bounds__(256) usum_kernel(const float* __restrict__ dlogit)
{
    int bx  = blockIdx.x;
    int j   = bx & 31;
    int bh  = (bx >> 5) & 15;
    int dir = bx >> 9;
    int h   = bh & 7;
    float lam = 1.f / (1.f + expf(-dlogit[h]));

    __shared__ float sK[CH_ * HD_];
    __shared__ float sV[CH_ * HD_];
    __shared__ float w [CH_];

    int tid = threadIdx.x;
    if (tid < CH_) w[tid] = powf(lam, (float)(CH_ - 1 - tid));

    int lrow = tid >> 2;
    int lseg = (tid & 3) * 16;
    int pt = dir ? (T_ - 1 - (j * CH_ + lrow)) : (j * CH_ + lrow);
    const float* Kg = g_QKV + QKVO     + (size_t)bh * T_ * HD_;
    const float* Vg = g_QKV + 2*QKVO   + (size_t)bh * T_ * HD_;
    {
        const float4* kr = (const float4*)(Kg + (size_t)pt * HD_ + lseg);
        const float4* vr = (const float4*)(Vg + (size_t)pt * HD_ + lseg);
        float4* sk = (float4*)(sK + lrow * HD_ + lseg);
        float4* sv = (float4*)(sV + lrow * HD_ + lseg);
        sk[0]=kr[0]; sk[1]=kr[1]; sk[2]=kr[2]; sk[3]=kr[3];
        sv[0]=vr[0]; sv[1]=vr[1]; sv[2]=vr[2]; sv[3]=vr[3];
    }
    __syncthreads();

    int d = tid & 63, c = tid >> 6;
    int e0 = c * 16;
    float acc[16];
#pragma unroll
    for (int i = 0; i < 16; i++) acc[i] = 0.f;
    float zacc = 0.f;

#pragma unroll 4
    for (int s = 0; s < CH_; s++){
        float kk = sK[s * HD_ + d] * w[s];
        zacc += kk;
        const float4* vv = (const float4*)(sV + s * HD_ + e0);
        float4 a0 = vv[0], a1 = vv[1], a2 = vv[2], a3 = vv[3];
        acc[0] = fmaf(kk, a0.x, acc[0]);  acc[1] = fmaf(kk, a0.y, acc[1]);
        acc[2] = fmaf(kk, a0.z, acc[2]);  acc[3] = fmaf(kk, a0.w, acc[3]);
        acc[4] = fmaf(kk, a1.x, acc[4]);  acc[5] = fmaf(kk, a1.y, acc[5]);
        acc[6] = fmaf(kk, a1.z, acc[6]);  acc[7] = fmaf(kk, a1.w, acc[7]);
        acc[8] = fmaf(kk, a2.x, acc[8]);  acc[9] = fmaf(kk, a2.y, acc[9]);
        acc[10]= fmaf(kk, a2.z, acc[10]); acc[11]= fmaf(kk, a2.w, acc[11]);
        acc[12]= fmaf(kk, a3.x, acc[12]); acc[13]= fmaf(kk, a3.y, acc[13]);
        acc[14]= fmaf(kk, a3.z, acc[14]); acc[15]= fmaf(kk, a3.w, acc[15]);
    }

    float* U = g_U + (size_t)((dir * NBH_ + bh) * NCH_ + j) * (HD_ * HD_);
#pragma unroll
    for (int i = 0; i < 16; i++) U[(e0 + i) * 64 + d] = acc[i];
    if (c == 0)
        g_zU[(size_t)((dir * NBH_ + bh) * NCH_ + j) * HD_ + d] = zacc;
}

// ---------------------------------------------------------------------------
// Scan level 2: sweep (validated R10)
// ---------------------------------------------------------------------------
__global__ void __launch_bounds__(256) sweep_kernel(const float* __restrict__ dlogit)
{
    int bx  = blockIdx.x;
    int seg = bx & 15;
    int bh  = (bx >> 4) & 15;
    int dir = bx >> 8;
    int h   = bh & 7;
    float lam  = 1.f / (1.f + expf(-dlogit[h]));
    float lamC = powf(lam, (float)CH_);

    int el = seg * 256 + threadIdx.x;
    size_t base = (size_t)((dir * NBH_ + bh) * NCH_) * (HD_ * HD_);
    float S = 0.f;
#pragma unroll
    for (int jj = 0; jj < NCH_; jj++){
        size_t o = base + (size_t)jj * (HD_ * HD_) + el;
        float u = g_U[o];
        g_Schk[o] = S;
        S = fmaf(lamC, S, u);
    }
    if (seg == 0 && threadIdx.x < HD_){
        int d = threadIdx.x;
        size_t zb = (size_t)((dir * NBH_ + bh) * NCH_) * HD_;
        float z = 0.f;
#pragma unroll
        for (int jj = 0; jj < NCH_; jj++){
            float zu = g_zU[zb + jj * HD_ + d];
            g_zchk[zb + jj * HD_ + d] = z;
            z = fmaf(lamC, z, zu);
        }
    }
}

// ------------------------- chunk kernel (validated) --------------------------
#define SOFF_Q   0
#define SOFF_K   4160
#define SOFF_A   8320
#define SOFF_S   12480
#define SOFF_V   16640
#define SOFF_ZP  20736
#define SOFF_DG  20800
#define SOFF_LP  20864
#define P2_SMEM_BYTES ((20864 + 80) * 4)

__global__ void __launch_bounds__(256) chunk_kernel(const float* __restrict__ dlogit)
{
    extern __shared__ float sm[];
    float* sQ  = sm + SOFF_Q;
    float* sK  = sm + SOFF_K;
    float* sA  = sm + SOFF_A;
    float* sS  = sm + SOFF_S;
    float* sV  = sm + SOFF_V;
    float* szp = sm + SOFF_ZP;
    float* sdg = sm + SOFF_DG;
    float* slp = sm + SOFF_LP;

    int bx  = blockIdx.x;
    int j   = bx & 31;
    int bh  = (bx >> 5) & 15;
    int dir = bx >> 9;
    int h   = bh & 7;
    float lam = 1.f / (1.f + expf(-dlogit[h]));

    int tid = threadIdx.x;
    if (tid <= CH_) slp[tid] = powf(lam, (float)tid);

    const float* Qg  = g_QKV            + (size_t)bh * T_ * HD_;
    const float* Kg  = g_QKV + QKVO     + (size_t)bh * T_ * HD_;
    const float* Vg  = g_QKV + 2*QKVO   + (size_t)bh * T_ * HD_;
    const float* Sin = g_Schk + (size_t)((dir * NBH_ + bh) * NCH_ + j) * (HD_ * HD_);
    const float* zin = g_zchk + (size_t)((dir * NBH_ + bh) * NCH_ + j) * HD_;

    int lrow = tid >> 2;
    int lseg = (tid & 3) * 16;
    int pt0 = dir ? (T_ - 1 - (j * CH_ + lrow)) : (j * CH_ + lrow);

#pragma unroll 4
    for (int i = 0; i < 16; i++) {
        sQ[lrow * 65 + lseg + i] = Qg[(size_t)pt0 * HD_ + lseg + i];
        sK[lrow * 65 + lseg + i] = Kg[(size_t)pt0 * HD_ + lseg + i];
    }
    {
        float4* svr = (float4*)(sV + lrow * 64 + lseg);
        const float4* vr = (const float4*)(Vg + (size_t)pt0 * HD_ + lseg);
        svr[0]=vr[0]; svr[1]=vr[1]; svr[2]=vr[2]; svr[3]=vr[3];
    }
#pragma unroll 4
    for (int i = 0; i < 16; i++) {
        int idx = tid * 16 + i;
        int e = idx >> 6, dd = idx & 63;
        sS[e * 65 + dd] = Sin[idx];
    }
    if (tid < 64) szp[tid] = zin[tid];
    __syncthreads();

    {
        int ty = tid >> 4, tx = tid & 15;
        int r0 = ty * 4, c0 = tx * 4;
        float acc[4][4];
#pragma unroll
        for (int i = 0; i < 4; i++)
#pragma unroll
            for (int jc = 0; jc < 4; jc++) acc[i][jc] = 0.f;

        for (int d = 0; d < 64; d++) {
            float q0 = sQ[(r0+0)*65+d], q1 = sQ[(r0+1)*65+d];
            float q2 = sQ[(r0+2)*65+d], q3 = sQ[(r0+3)*65+d];
            float k0 = sK[(c0+0)*65+d], k1 = sK[(c0+1)*65+d];
            float k2 = sK[(c0+2)*65+d], k3 = sK[(c0+3)*65+d];
            acc[0][0]=fmaf(q0,k0,acc[0][0]); acc[0][1]=fmaf(q0,k1,acc[0][1]);
            acc[0][2]=fmaf(q0,k2,acc[0][2]); acc[0][3]=fmaf(q0,k3,acc[0][3]);
            acc[1][0]=fmaf(q1,k0,acc[1][0]); acc[1][1]=fmaf(q1,k1,acc[1][1]);
            acc[1][2]=fmaf(q1,k2,acc[1][2]); acc[1][3]=fmaf(q1,k3,acc[1][3]);
            acc[2][0]=fmaf(q2,k0,acc[2][0]); acc[2][1]=fmaf(q2,k1,acc[2][1]);
            acc[2][2]=fmaf(q2,k2,acc[2][2]); acc[2][3]=fmaf(q2,k3,acc[2][3]);
            acc[3][0]=fmaf(q3,k0,acc[3][0]); acc[3][1]=fmaf(q3,k1,acc[3][1]);
            acc[3][2]=fmaf(q3,k2,acc[3][2]); acc[3][3]=fmaf(q3,k3,acc[3][3]);
        }
#pragma unroll
        for (int i = 0; i < 4; i++) {
            int r = r0 + i;
#pragma unroll
            for (int jc = 0; jc < 4; jc++) {
                int cc = c0 + jc;
                float p = acc[i][jc];
                if (r == cc) sdg[r] = p;
                sA[r * 65 + cc] = (r >= cc) ? p * slp[r - cc] : 0.f;
            }
        }
    }
    __syncthreads();

    {
        int rr = (tid >> 3) * 2;
        int c0 = (tid & 7) * 8;
        float aA[2][8], aI[2][8];
#pragma unroll
        for (int i = 0; i < 2; i++)
#pragma unroll
            for (int jc = 0; jc < 8; jc++) { aA[i][jc] = 0.f; aI[i][jc] = 0.f; }
        float cs0 = 0.f, cs1 = 0.f, cq0 = 0.f, cq1 = 0.f;

        for (int s = 0; s < 64; s++) {
            float a0 = sA[rr * 65 + s];
            float a1 = sA[(rr + 1) * 65 + s];
            cs0 += a0; cs1 += a1;
            float4 v0 = *(const float4*)(sV + s * 64 + c0);
            float4 v1 = *(const float4*)(sV + s * 64 + c0 + 4);
            aA[0][0]=fmaf(a0,v0.x,aA[0][0]); aA[0][1]=fmaf(a0,v0.y,aA[0][1]);
            aA[0][2]=fmaf(a0,v0.z,aA[0][2]); aA[0][3]=fmaf(a0,v0.w,aA[0][3]);
            aA[0][4]=fmaf(a0,v1.x,aA[0][4]); aA[0][5]=fmaf(a0,v1.y,aA[0][5]);
            aA[0][6]=fmaf(a0,v1.z,aA[0][6]); aA[0][7]=fmaf(a0,v1.w,aA[0][7]);
            aA[1][0]=fmaf(a1,v0.x,aA[1][0]); aA[1][1]=fmaf(a1,v0.y,aA[1][1]);
            aA[1][2]=fmaf(a1,v0.z,aA[1][2]); aA[1][3]=fmaf(a1,v0.w,aA[1][3]);
            aA[1][4]=fmaf(a1,v1.x,aA[1][4]); aA[1][5]=fmaf(a1,v1.y,aA[1][5]);
            aA[1][6]=fmaf(a1,v1.z,aA[1][6]); aA[1][7]=fmaf(a1,v1.w,aA[1][7]);
        }
        for (int d = 0; d < 64; d++) {
            float q0 = sQ[rr * 65 + d];
            float q1 = sQ[(rr + 1) * 65 + d];
            cq0 = fmaf(q0, szp[d], cq0);
            cq1 = fmaf(q1, szp[d], cq1);
#pragma unroll
            for (int jc = 0; jc < 8; jc++) {
                float sv = sS[(c0 + jc) * 65 + d];
                aI[0][jc] = fmaf(q0, sv, aI[0][jc]);
                aI[1][jc] = fmaf(q1, sv, aI[1][jc]);
            }
        }

        float* Yg = g_Y + (size_t)(dir * NBH_ + bh) * T_ * HD_;
        float* Cg = g_C + (size_t)(dir * NBH_ + bh) * T_;
#pragma unroll
        for (int i = 0; i < 2; i++) {
            int r = rr + i;
            int pt = dir ? (T_ - 1 - (j * CH_ + r)) : (j * CH_ + r);
            float lf = slp[r + 1];
            float qk = sdg[r];
#pragma unroll
            for (int jc = 0; jc < 8; jc++) {
                int e = c0 + jc;
                Yg[(size_t)pt * HD_ + e] = aA[i][jc] + lf * aI[i][jc] - 0.5f * qk * sV[r * 64 + e];
            }
            if (c0 == 0)
                Cg[pt] = (i ? cs1 : cs0) + lf * (i ? cq1 : cq0) - 0.5f * qk;
        }
    }
}

// ------------------------- combine + split ---------------------------------
__global__ void __launch_bounds__(256) combine_kernel()
{
    int i = blockIdx.x * 256 + threadIdx.x;
    int e  = i & 63;
    int tt = (i >> 6) & (T_ - 1);
    int bh = i >> 17;
    int b  = bh >> 3;
    int h  = bh & 7;

    float yf  = g_Y[i];
    float ybk = g_Y[i + NBH_ * T_ * HD_];
    float cf  = g_C[bh * T_ + tt];
    float cbk = g_C[bh * T_ + tt + NBH_ * T_];
    float v = (yf + ybk) / fmaxf(cf + cbk, 1e-6f);
    size_t dst = ((size_t)(b * T_ + tt) * D_) + h * HD_ + e;
    __nv_bfloat16 hv = __float2bfloat16(v);
    g_ath[dst] = hv;
    g_atl[dst] = __float2bfloat16(v - __bfloat162float(hv));
}

// ------------------------- launcher ----------------------------------------
extern "C" void kernel_launch(void* const* d_in, const int* in_sizes, int n_in,
                              void* d_out, int out_size)
{
    const float* x    = (const float*)d_in[0];
    const float* Wq   = (const float*)d_in[2];
    const float* Wk   = (const float*)d_in[3];
    const float* Wv   = (const float*)d_in[4];
    const float* Wo   = (const float*)d_in[5];
    const float* bo   = (const float*)d_in[6];
    const float* g1   = (const float*)d_in[7];
    const float* b1   = (const float*)d_in[8];
    const float* g2   = (const float*)d_in[9];
    const float* b2   = (const float*)d_in[10];
    const float* W1   = (const float*)d_in[11];
    const float* bf1  = (const float*)d_in[12];
    const float* W2   = (const float*)d_in[13];
    const float* bf2  = (const float*)d_in[14];
    const float* dlog = (const float*)d_in[15];
    float* out = (float*)d_out;

#define SYM(p, s) cudaGetSymbolAddress((void**)&p, s)
    __nv_bfloat16 *xnh,*xnl,*ath,*atl,*h2h,*h2l,*f1h,*f1l;
    __nv_bfloat16 *wqkvh,*wqkvl,*woh,*wol,*w1h,*w1l,*w2h,*w2l;
    float *QKV,*x2;
    SYM(xnh,g_xnh); SYM(xnl,g_xnl); SYM(ath,g_ath); SYM(atl,g_atl);
    SYM(h2h,g_h2h); SYM(h2l,g_h2l); SYM(f1h,g_f1h); SYM(f1l,g_f1l);
    SYM(wqkvh,g_wqkvh); SYM(wqkvl,g_wqkvl);
    SYM(woh,g_woh); SYM(wol,g_wol);
    SYM(w1h,g_w1h); SYM(w1l,g_w1l); SYM(w2h,g_w2h); SYM(w2l,g_w2l);
    SYM(QKV,g_QKV); SYM(x2,g_x2);
#undef SYM

    cudaFuncSetAttribute(tc_gemm<4,512>,   cudaFuncAttributeMaxDynamicSharedMemorySize, GEMM_SMEM);
    cudaFuncSetAttribute(tc_gemm<3,512>,   cudaFuncAttributeMaxDynamicSharedMemorySize, GEMM_SMEM);
    cudaFuncSetAttribute(tc_gemm64<512>,   cudaFuncAttributeMaxDynamicSharedMemorySize, GEMM64_SMEM);
    cudaFuncSetAttribute(tc_gemm64<2048>,  cudaFuncAttributeMaxDynamicSharedMemorySize, GEMM64_SMEM);
    cudaFuncSetAttribute(chunk_kernel,     cudaFuncAttributeMaxDynamicSharedMemorySize, P2_SMEM_BYTES);

    dim3 blk(256);
    dim3 gQKV((3*D_) / 128, M_ / 128);  // (12, 32) = 384 CTAs
    dim3 gD64(D_ / 128, M_ / 64);       // (4, 64)  = 256 CTAs
    dim3 gF(F_ / 128, M_ / 128);        // (16, 32) = 512 CTAs

    // 0) all weight splits, one launch
    split_all_kernel<<<3145728/256, blk>>>(Wq, Wk, Wv, Wo, W1, W2);
    // 1) LN1 (+split)
    ln_split_kernel<<<M_, blk>>>(x, g1, b1, xnh, xnl);
    // 2) fused Q/K/V projection — one launch, 128x128 tiles, 384 CTAs
    tc_gemm<4,512><<<gQKV, blk, GEMM_SMEM>>>(xnh, xnl, wqkvh, wqkvl, 3*D_,
                                             nullptr, QKV, nullptr, nullptr);
    // 3) two-level scan + per-chunk outputs
    usum_kernel<<<2 * NBH_ * NCH_, blk>>>(dlog);
    sweep_kernel<<<2 * NBH_ * 16, blk>>>(dlog);
    chunk_kernel<<<2 * NBH_ * NCH_, blk, P2_SMEM_BYTES>>>(dlog);
    // 4) combine (+split)
    combine_kernel<<<(NBH_ * T_ * HD_) / 256, blk>>>();
    // 5) Wo + bias + residual -> fp32 x2   (64-row tiles, 256 CTAs)
    tc_gemm64<512><<<gD64, blk, GEMM64_SMEM>>>(ath, atl, woh, wol, D_, bo, x, x2);
    // 6) LN2 (+split)
    ln_split_kernel<<<M_, blk>>>(x2, g2, b2, h2h, h2l);
    // 7) FFN up + GELU -> split bf16
    tc_gemm<3,512><<<gF, blk, GEMM_SMEM>>>(h2h, h2l, w1h, w1l, F_, bf1, nullptr, f1h, f1l);
    // 8) FFN down + bias + residual -> final output (64-row tiles, 256 CTAs)
    tc_gemm64<2048><<<gD64, blk, GEMM64_SMEM>>>(f1h, f1l, w2h, w2l, D_, bf2, x2, out);
}

// round 12
// speedup vs baseline: 1.2206x; 1.0885x over previous
#include <cuda_runtime.h>
#include <cuda_bf16.h>
#include <math.h>
#include <stdint.h>

#define B_   2
#define T_   2048
#define D_   512
#define H_   8
#define HD_  64
#define F_   2048
#define M_   (B_*T_)
#define CH_  64
#define NCH_ (T_/CH_)
#define NBH_ (B_*H_)
#define QKVO (NBH_*T_*HD_)

// ------------------------- scratch globals ---------------------------------
__device__ __nv_bfloat16 g_xnh[M_*D_], g_xnl[M_*D_];
__device__ __nv_bfloat16 g_ath[M_*D_], g_atl[M_*D_];
__device__ __nv_bfloat16 g_h2h[M_*D_], g_h2l[M_*D_];
__device__ __nv_bfloat16 g_f1h[M_*F_], g_f1l[M_*F_];
__device__ __nv_bfloat16 g_wqkvh[3*D_*D_], g_wqkvl[3*D_*D_];   // Wq|Wk|Wv rows
__device__ __nv_bfloat16 g_woh[D_*D_], g_wol[D_*D_];
__device__ __nv_bfloat16 g_w1h[F_*D_], g_w1l[F_*D_];
__device__ __nv_bfloat16 g_w2h[D_*F_], g_w2l[D_*F_];
__device__ float g_QKV[3*QKVO];                                // Q|K|V [b,h,t,e]
__device__ float g_x2[M_*D_];
__device__ float g_Schk[2*NBH_*NCH_*HD_*HD_];   // state entering each logical chunk
__device__ float g_zchk[2*NBH_*NCH_*HD_];
__device__ float g_U   [2*NBH_*NCH_*HD_*HD_];
__device__ float g_zU  [2*NBH_*NCH_*HD_];

// ------------------------- helpers -----------------------------------------
static __device__ __forceinline__ uint32_t stou(const void* p){
    uint32_t a;
    asm("{ .reg .u64 t; cvta.to.shared.u64 t, %1; cvt.u32.u64 %0, t; }" : "=r"(a) : "l"(p));
    return a;
}
static __device__ __forceinline__ void cp16(uint32_t dst, const void* src){
    asm volatile("cp.async.cg.shared.global [%0], [%1], 16;" :: "r"(dst), "l"(src));
}
static __device__ __forceinline__ void ldmA(uint32_t* a, uint32_t addr){
    asm volatile("ldmatrix.sync.aligned.m8n8.x4.shared.b16 {%0,%1,%2,%3}, [%4];"
        : "=r"(a[0]),"=r"(a[1]),"=r"(a[2]),"=r"(a[3]) : "r"(addr));
}
static __device__ __forceinline__ void ldmB(uint32_t* b, uint32_t addr){
    asm volatile("ldmatrix.sync.aligned.m8n8.x2.shared.b16 {%0,%1}, [%2];"
        : "=r"(b[0]),"=r"(b[1]) : "r"(addr));
}
static __device__ __forceinline__ void mma16816(float* c, const uint32_t* a, const uint32_t* b){
    asm volatile("mma.sync.aligned.m16n8k16.row.col.f32.bf16.bf16.f32 "
        "{%0,%1,%2,%3}, {%4,%5,%6,%7}, {%8,%9}, {%0,%1,%2,%3};"
        : "+f"(c[0]),"+f"(c[1]),"+f"(c[2]),"+f"(c[3])
        : "r"(a[0]),"r"(a[1]),"r"(a[2]),"r"(a[3]), "r"(b[0]),"r"(b[1]));
}

#define ROWB  144
#define ATILE 18432
#define STGB  36864
#define GEMM_SMEM (2*STGB)
#define BOFF64  9216
#define STGB64  27648
#define GEMM64_SMEM (2*STGB64)

// ---------------------------------------------------------------------------
// 128x128 split-bf16 GEMM (K'=3K), 2-stage (validated R8).
// MODE: 3=bias+gelu->split bf16   4=fused QKV scatter (elu for n<1024)
// ---------------------------------------------------------------------------
template<int MODE, int KDIM>
__global__ void __launch_bounds__(256,2) tc_gemm(
    const __nv_bfloat16* __restrict__ Ah, const __nv_bfloat16* __restrict__ Al,
    const __nv_bfloat16* __restrict__ Bh, const __nv_bfloat16* __restrict__ Bl,
    int N, const float* __restrict__ bias,
    float* __restrict__ outF,
    __nv_bfloat16* __restrict__ outH, __nv_bfloat16* __restrict__ outL)
{
    extern __shared__ char dyns[];
    uint32_t sb = stou(dyns);

    int tid = threadIdx.x;
    int lane = tid & 31, w = tid >> 5;
    int warp_m = w >> 2, warp_n = w & 3;
    int m0 = blockIdx.y * 128;
    int n0 = blockIdx.x * 128;

    float acc[4][4][4];
#pragma unroll
    for (int i=0;i<4;i++)
#pragma unroll
        for (int j=0;j<4;j++)
#pragma unroll
            for (int k=0;k<4;k++) acc[i][j][k] = 0.f;

    const int NIT = 3*KDIM/64;

    auto fill = [&](int itf){
        int st = itf & 1;
        int kp = itf * 64;
        int pass = kp / KDIM;
        int koff = kp - pass*KDIM;
        const __nv_bfloat16* pA = (pass==1)? Al : Ah;
        const __nv_bfloat16* pB = (pass==2)? Bl : Bh;
        uint32_t base = sb + st*STGB;
#pragma unroll
        for (int i=0;i<8;i++){
            int q = tid + i*256;
            int isB = q >> 10;
            int r   = (q >> 3) & 127;
            int c16 = q & 7;
            const __nv_bfloat16* src =
                (isB ? (pB + (size_t)(n0+r)*KDIM) : (pA + (size_t)(m0+r)*KDIM)) + koff + c16*8;
            cp16(base + isB*ATILE + r*ROWB + c16*16, src);
        }
        asm volatile("cp.async.commit_group;" ::: "memory");
    };

    uint32_t aBase = (uint32_t)((warp_m*64 + (lane & 15))*ROWB + ((lane >> 4) << 4));
    uint32_t bBase = (uint32_t)(ATILE + (warp_n*32 + (lane & 7))*ROWB + (((lane >> 3) & 1) << 4));

    fill(0);
    for (int it=0; it<NIT; ++it){
        if (it+1 < NIT){
            fill(it+1);
            asm volatile("cp.async.wait_group 1;" ::: "memory");
        } else {
            asm volatile("cp.async.wait_group 0;" ::: "memory");
        }
        __syncthreads();
        uint32_t stg = sb + (it&1)*STGB;
#pragma unroll
        for (int kk=0; kk<64; kk+=16){
            uint32_t afrag[4][4], bfrag[4][2];
#pragma unroll
            for (int mt=0;mt<4;mt++) ldmA(afrag[mt], stg + aBase + mt*(16*ROWB) + kk*2);
#pragma unroll
            for (int nt=0;nt<4;nt++) ldmB(bfrag[nt], stg + bBase + nt*(8*ROWB) + kk*2);
#pragma unroll
            for (int mt=0;mt<4;mt++)
#pragma unroll
                for (int nt=0;nt<4;nt++) mma16816(acc[mt][nt], afrag[mt], bfrag[nt]);
        }
        __syncthreads();
    }

    int mb = m0 + warp_m*64;
    int nb = n0 + warp_n*32;
#pragma unroll
    for (int mt=0; mt<4; mt++){
#pragma unroll
        for (int half=0; half<2; half++){
            int m = mb + mt*16 + (lane>>2) + half*8;
            int bb = m >> 11, tt = m & (T_-1);
#pragma unroll
            for (int nt=0; nt<4; nt++){
                int n = nb + nt*8 + (lane&3)*2;
                float v0 = acc[mt][nt][half*2];
                float v1 = acc[mt][nt][half*2+1];
                if (MODE == 4){
                    int mat = n >> 9;              // 0=Q 1=K 2=V
                    if (mat < 2){
                        v0 = v0>0.f ? v0+1.f : expf(v0);
                        v1 = v1>0.f ? v1+1.f : expf(v1);
                    }
                    int hh = (n >> 6) & 7, ee = n & 63;
                    float* dst = outF + (size_t)mat*QKVO
                               + ((((size_t)(bb*H_ + hh))*T_ + tt)<<6) + ee;
                    float2 o; o.x=v0; o.y=v1;
                    *(float2*)dst = o;
                } else {   // MODE 3: bias + exact GELU -> split bf16
                    size_t idx = (size_t)m*N + n;
                    float a = v0 + bias[n];
                    float b = v1 + bias[n+1];
                    a = 0.5f*a*(1.f+erff(a*0.70710678118654752f));
                    b = 0.5f*b*(1.f+erff(b*0.70710678118654752f));
                    __nv_bfloat16 ha=__float2bfloat16(a), hb=__float2bfloat16(b);
                    float la = a-__bfloat162float(ha), lb = b-__bfloat162float(hb);
                    uint32_t hp = (uint32_t)__bfloat16_as_ushort(ha) |
                                  ((uint32_t)__bfloat16_as_ushort(hb)<<16);
                    uint32_t lp = (uint32_t)__bfloat16_as_ushort(__float2bfloat16(la)) |
                                  ((uint32_t)__bfloat16_as_ushort(__float2bfloat16(lb))<<16);
                    *(uint32_t*)(outH + idx) = hp;
                    *(uint32_t*)(outL + idx) = lp;
                }
            }
        }
    }
}

// ---------------------------------------------------------------------------
// 64x128 split-bf16 GEMM, 2-stage, 3 CTAs/SM (validated R11). bias+res->fp32.
// ---------------------------------------------------------------------------
template<int KDIM>
__global__ void __launch_bounds__(256,3) tc_gemm64(
    const __nv_bfloat16* __restrict__ Ah, const __nv_bfloat16* __restrict__ Al,
    const __nv_bfloat16* __restrict__ Bh, const __nv_bfloat16* __restrict__ Bl,
    int N, const float* __restrict__ bias, const float* __restrict__ res,
    float* __restrict__ outF)
{
    extern __shared__ char dyns[];
    uint32_t sb = stou(dyns);

    int tid = threadIdx.x;
    int lane = tid & 31, w = tid >> 5;
    int warp_m = w >> 2, warp_n = w & 3;
    int m0 = blockIdx.y * 64;
    int n0 = blockIdx.x * 128;

    float acc[2][4][4];
#pragma unroll
    for (int i=0;i<2;i++)
#pragma unroll
        for (int j=0;j<4;j++)
#pragma unroll
            for (int k=0;k<4;k++) acc[i][j][k] = 0.f;

    const int NIT = 3*KDIM/64;

    auto fill = [&](int itf){
        int st = itf & 1;
        int kp = itf * 64;
        int pass = kp / KDIM;
        int koff = kp - pass*KDIM;
        const __nv_bfloat16* pA = (pass==1)? Al : Ah;
        const __nv_bfloat16* pB = (pass==2)? Bl : Bh;
        uint32_t base = sb + st*STGB64;
#pragma unroll
        for (int i=0;i<6;i++){
            int q = tid + i*256;
            if (q < 512){
                int r = q >> 3, c16 = q & 7;
                cp16(base + r*ROWB + c16*16,
                     pA + (size_t)(m0+r)*KDIM + koff + c16*8);
            } else {
                int q2 = q - 512;
                int r = q2 >> 3, c16 = q2 & 7;
                cp16(base + BOFF64 + r*ROWB + c16*16,
                     pB + (size_t)(n0+r)*KDIM + koff + c16*8);
            }
        }
        asm volatile("cp.async.commit_group;" ::: "memory");
    };

    uint32_t aBase = (uint32_t)((warp_m*32 + (lane & 15))*ROWB + ((lane >> 4) << 4));
    uint32_t bBase = (uint32_t)(BOFF64 + (warp_n*32 + (lane & 7))*ROWB + (((lane >> 3) & 1) << 4));

    fill(0);
    for (int it=0; it<NIT; ++it){
        if (it+1 < NIT){
            fill(it+1);
            asm volatile("cp.async.wait_group 1;" ::: "memory");
        } else {
            asm volatile("cp.async.wait_group 0;" ::: "memory");
        }
        __syncthreads();
        uint32_t stg = sb + (it&1)*STGB64;
#pragma unroll
        for (int kk=0; kk<64; kk+=16){
            uint32_t afrag[2][4], bfrag[4][2];
#pragma unroll
            for (int mt=0;mt<2;mt++) ldmA(afrag[mt], stg + aBase + mt*(16*ROWB) + kk*2);
#pragma unroll
            for (int nt=0;nt<4;nt++) ldmB(bfrag[nt], stg + bBase + nt*(8*ROWB) + kk*2);
#pragma unroll
            for (int mt=0;mt<2;mt++)
#pragma unroll
                for (int nt=0;nt<4;nt++) mma16816(acc[mt][nt], afrag[mt], bfrag[nt]);
        }
        __syncthreads();
    }

    int mb = m0 + warp_m*32;
    int nb = n0 + warp_n*32;
#pragma unroll
    for (int mt=0; mt<2; mt++){
#pragma unroll
        for (int half=0; half<2; half++){
            int m = mb + mt*16 + (lane>>2) + half*8;
#pragma unroll
            for (int nt=0; nt<4; nt++){
                int n = nb + nt*8 + (lane&3)*2;
                float v0 = acc[mt][nt][half*2];
                float v1 = acc[mt][nt][half*2+1];
                size_t idx = (size_t)m*N + n;
                float2 rv = *(const float2*)(res + idx);
                float2 o;
                o.x = v0 + bias[n]   + rv.x;
                o.y = v1 + bias[n+1] + rv.y;
                *(float2*)(outF + idx) = o;
            }
        }
    }
}

// ------------------------- batched weight split ------------------------------
__global__ void __launch_bounds__(256) split_all_kernel(
    const float* __restrict__ Wq, const float* __restrict__ Wk,
    const float* __restrict__ Wv, const float* __restrict__ Wo,
    const float* __restrict__ W1, const float* __restrict__ W2)
{
    int i = blockIdx.x * 256 + threadIdx.x;
    float v; __nv_bfloat16 *dh, *dl; int j;
    if (i < 786432){
        int which = i >> 18; j = i & 262143;
        v = (which==0 ? Wq : which==1 ? Wk : Wv)[j];
        dh = g_wqkvh + i; dl = g_wqkvl + i;
    } else if (i < 1048576){
        j = i - 786432; v = Wo[j]; dh = g_woh + j; dl = g_wol + j;
    } else if (i < 2097152){
        j = i - 1048576; v = W1[j]; dh = g_w1h + j; dl = g_w1l + j;
    } else {
        j = i - 2097152; v = W2[j]; dh = g_w2h + j; dl = g_w2l + j;
    }
    __nv_bfloat16 hh = __float2bfloat16(v);
    *dh = hh;
    *dl = __float2bfloat16(v - __bfloat162float(hh));
}

// ------------------------- LayerNorm + split --------------------------------
__global__ void __launch_bounds__(256) ln_split_kernel(
    const float* __restrict__ x, const float* __restrict__ g,
    const float* __restrict__ b, __nv_bfloat16* __restrict__ yh,
    __nv_bfloat16* __restrict__ yl)
{
    int row = blockIdx.x;
    const float* xr = x + (size_t)row * D_;
    int tid = threadIdx.x;
    float v0 = xr[tid], v1 = xr[tid + 256];
    float s  = v0 + v1, ss = v0*v0 + v1*v1;
    __shared__ float sh[16];
#pragma unroll
    for (int o = 16; o; o >>= 1) {
        s  += __shfl_xor_sync(0xffffffffu, s,  o);
        ss += __shfl_xor_sync(0xffffffffu, ss, o);
    }
    int w = tid >> 5;
    if ((tid & 31) == 0) { sh[w] = s; sh[w + 8] = ss; }
    __syncthreads();
    float S = 0.f, SS = 0.f;
#pragma unroll
    for (int i = 0; i < 8; i++) { S += sh[i]; SS += sh[8 + i]; }
    float mean = S * (1.0f / D_);
    float rstd = rsqrtf(SS * (1.0f / D_) - mean*mean + 1e-5f);
    size_t base = (size_t)row * D_;
    float o0 = (v0 - mean) * rstd * g[tid]       + b[tid];
    float o1 = (v1 - mean) * rstd * g[tid + 256] + b[tid + 256];
    __nv_bfloat16 h0 = __float2bfloat16(o0), h1 = __float2bfloat16(o1);
    yh[base + tid]       = h0;
    yh[base + tid + 256] = h1;
    yl[base + tid]       = __float2bfloat16(o0 - __bfloat162float(h0));
    yl[base + tid + 256] = __float2bfloat16(o1 - __bfloat162float(h1));
}

// ---------------------------------------------------------------------------
// Scan level 1 (DUAL direction): per-physical-chunk partials for BOTH dirs
// from one shared K/V load. grid = 16*32 = 512 blocks.
//   U_f[e][d] = sum_s lam^(C-1-s) k_s[d] v_s[e]   -> g_U[0][bh][j]
//   U_b[e][d] = sum_s lam^(s)     k_s[d] v_s[e]   -> g_U[1][bh][NCH-1-j]
// ---------------------------------------------------------------------------
__global__ void __launch_bounds__(256) usum_dual_kernel(const float* __restrict__ dlogit)
{
    int bx  = blockIdx.x;
    int j   = bx & 31;
    int bh  = bx >> 5;
    int h   = bh & 7;
    float lam = 1.f / (1.f + expf(-dlogit[h]));

    __shared__ float sK[CH_ * HD_];
    __shared__ float sV[CH_ * HD_];
    __shared__ float wf[CH_], wb[CH_];

    int tid = threadIdx.x;
    if (tid < CH_){
        wf[tid] = powf(lam, (float)(CH_ - 1 - tid));
        wb[tid] = powf(lam, (float)tid);
    }

    int lrow = tid >> 2;
    int lseg = (tid & 3) * 16;
    int pt = j * CH_ + lrow;                       // physical row
    const float* Kg = g_QKV + QKVO     + (size_t)bh * T_ * HD_;
    const float* Vg = g_QKV + 2*QKVO   + (size_t)bh * T_ * HD_;
    {
        const float4* kr = (const float4*)(Kg + (size_t)pt * HD_ + lseg);
        const float4* vr = (const float4*)(Vg + (size_t)pt * HD_ + lseg);
        float4* sk = (float4*)(sK + lrow * HD_ + lseg);
        float4* sv = (float4*)(sV + lrow * HD_ + lseg);
        sk[0]=kr[0]; sk[1]=kr[1]; sk[2]=kr[2]; sk[3]=kr[3];
        sv[0]=vr[0]; sv[1]=vr[1]; sv[2]=vr[2]; sv[3]=vr[3];
    }
    __syncthreads();

    int d = tid & 63, c = tid >> 6;
    int e0 = c * 16;
    float aF[16], aB[16];
#pragma unroll
    for (int i = 0; i < 16; i++){ aF[i] = 0.f; aB[i] = 0.f; }
    float zF = 0.f, zB = 0.f;

#pragma unroll 4
    for (int s = 0; s < CH_; s++){
        float kr = sK[s * HD_ + d];
        float kf = kr * wf[s];
        float kb = kr * wb[s];
        zF += kf; zB += kb;
        const float4* vv = (const float4*)(sV + s * HD_ + e0);
        float4 a0 = vv[0], a1 = vv[1], a2 = vv[2], a3 = vv[3];
        aF[0]=fmaf(kf,a0.x,aF[0]); aB[0]=fmaf(kb,a0.x,aB[0]);
        aF[1]=fmaf(kf,a0.y,aF[1]); aB[1]=fmaf(kb,a0.y,aB[1]);
        aF[2]=fmaf(kf,a0.z,aF[2]); aB[2]=fmaf(kb,a0.z,aB[2]);
        aF[3]=fmaf(kf,a0.w,aF[3]); aB[3]=fmaf(kb,a0.w,aB[3]);
        aF[4]=fmaf(kf,a1.x,aF[4]); aB[4]=fmaf(kb,a1.x,aB[4]);
        aF[5]=fmaf(kf,a1.y,aF[5]); aB[5]=fmaf(kb,a1.y,aB[5]);
        aF[6]=fmaf(kf,a1.z,aF[6]); aB[6]=fmaf(kb,a1.z,aB[6]);
        aF[7]=fmaf(kf,a1.w,aF[7]); aB[7]=fmaf(kb,a1.w,aB[7]);
        aF[8]=fmaf(kf,a2.x,aF[8]); aB[8]=fmaf(kb,a2.x,aB[8]);
        aF[9]=fmaf(kf,a2.y,aF[9]); aB[9]=fmaf(kb,a2.y,aB[9]);
        aF[10]=fmaf(kf,a2.z,aF[10]); aB[10]=fmaf(kb,a2.z,aB[10]);
        aF[11]=fmaf(kf,a2.w,aF[11]); aB[11]=fmaf(kb,a2.w,aB[11]);
        aF[12]=fmaf(kf,a3.x,aF[12]); aB[12]=fmaf(kb,a3.x,aB[12]);
        aF[13]=fmaf(kf,a3.y,aF[13]); aB[13]=fmaf(kb,a3.y,aB[13]);
        aF[14]=fmaf(kf,a3.z,aF[14]); aB[14]=fmaf(kb,a3.z,aB[14]);
        aF[15]=fmaf(kf,a3.w,aF[15]); aB[15]=fmaf(kb,a3.w,aB[15]);
    }

    float* Uf = g_U + (size_t)((0 * NBH_ + bh) * NCH_ + j) * (HD_ * HD_);
    float* Ub = g_U + (size_t)((1 * NBH_ + bh) * NCH_ + (NCH_ - 1 - j)) * (HD_ * HD_);
#pragma unroll
    for (int i = 0; i < 16; i++){
        Uf[(e0 + i) * 64 + d] = aF[i];
        Ub[(e0 + i) * 64 + d] = aB[i];
    }
    if (c == 0){
        g_zU[(size_t)((0 * NBH_ + bh) * NCH_ + j) * HD_ + d] = zF;
        g_zU[(size_t)((1 * NBH_ + bh) * NCH_ + (NCH_ - 1 - j)) * HD_ + d] = zB;
    }
}

// ---------------------------------------------------------------------------
// Scan level 2: sweep (validated R10, unchanged)
// ---------------------------------------------------------------------------
__global__ void __launch_bounds__(256) sweep_kernel(const float* __restrict__ dlogit)
{
    int bx  = blockIdx.x;
    int seg = bx & 15;
    int bh  = (bx >> 4) & 15;
    int dir = bx >> 8;
    int h   = bh & 7;
    float lam  = 1.f / (1.f + expf(-dlogit[h]));
    float lamC = powf(lam, (float)CH_);

    int el = seg * 256 + threadIdx.x;
    size_t base = (size_t)((dir * NBH_ + bh) * NCH_) * (HD_ * HD_);
    float S = 0.f;
#pragma unroll
    for (int jj = 0; jj < NCH_; jj++){
        size_t o = base + (size_t)jj * (HD_ * HD_) + el;
        float u = g_U[o];
        g_Schk[o] = S;
        S = fmaf(lamC, S, u);
    }
    if (seg == 0 && threadIdx.x < HD_){
        int d = threadIdx.x;
        size_t zb = (size_t)((dir * NBH_ + bh) * NCH_) * HD_;
        float z = 0.f;
#pragma unroll
        for (int jj = 0; jj < NCH_; jj++){
            float zu = g_zU[zb + jj * HD_ + d];
            g_zchk[zb + jj * HD_ + d] = z;
            z = fmaf(lamC, z, zu);
        }
    }
}

// ---------------------------------------------------------------------------
// Combined dual-direction chunk kernel + normalize + split-bf16 output.
// For physical chunk j:  P = Q K^T (once).
//   A[r,s] = P[r,s] * lam^|r-s|       (diag counted once; the two -0.5qk v
//                                      corrections cancel one diagonal copy)
//   Y[r]   = (A V)[r] + lam^(r+1) q_r S_f + lam^(C-r) q_r S_b
//   Cden   = rowsum(A)[r] + lam^(r+1) q.z_f + lam^(C-r) q.z_b
//   attn   = Y / max(Cden, 1e-6)  -> split bf16 [b,t,d]
// grid = 16*32 = 512 blocks.  States stored transposed [d][e] pitch 68.
// ---------------------------------------------------------------------------
#define COFF_Q   0
#define COFF_K   4160
#define COFF_P   8320
#define COFF_V   12480
#define COFF_SF  16576
#define COFF_SB  20928
#define COFF_ZF  25280
#define COFF_ZB  25344
#define COFF_LP  25408
#define CC_SMEM_BYTES ((25408 + 80) * 4)

__global__ void __launch_bounds__(256) chunk_comb_kernel(const float* __restrict__ dlogit)
{
    extern __shared__ float sm[];
    float* sQ  = sm + COFF_Q;     // [64][65]
    float* sK  = sm + COFF_K;     // [64][65]
    float* sP  = sm + COFF_P;     // [64][65] weighted
    float* sV  = sm + COFF_V;     // [64][64]
    float* sSf = sm + COFF_SF;    // [d][e] pitch 68
    float* sSb = sm + COFF_SB;
    float* szf = sm + COFF_ZF;    // [64]
    float* szb = sm + COFF_ZB;
    float* slp = sm + COFF_LP;    // lam^0..lam^64

    int bx  = blockIdx.x;
    int j   = bx & 31;
    int bh  = bx >> 5;
    int h   = bh & 7;
    float lam = 1.f / (1.f + expf(-dlogit[h]));

    int tid = threadIdx.x;
    if (tid <= CH_) slp[tid] = powf(lam, (float)tid);

    const float* Qg  = g_QKV            + (size_t)bh * T_ * HD_;
    const float* Kg  = g_QKV + QKVO     + (size_t)bh * T_ * HD_;
    const float* Vg  = g_QKV + 2*QKVO   + (size_t)bh * T_ * HD_;
    const float* Sfin = g_Schk + (size_t)((0 * NBH_ + bh) * NCH_ + j) * (HD_ * HD_);
    const float* Sbin = g_Schk + (size_t)((1 * NBH_ + bh) * NCH_ + (NCH_ - 1 - j)) * (HD_ * HD_);
    const float* zfin = g_zchk + (size_t)((0 * NBH_ + bh) * NCH_ + j) * HD_;
    const float* zbin = g_zchk + (size_t)((1 * NBH_ + bh) * NCH_ + (NCH_ - 1 - j)) * HD_;

    int lrow = tid >> 2;
    int lseg = (tid & 3) * 16;
    int pt0 = j * CH_ + lrow;                  // physical row

#pragma unroll 4
    for (int i = 0; i < 16; i++) {
        sQ[lrow * 65 + lseg + i] = Qg[(size_t)pt0 * HD_ + lseg + i];
        sK[lrow * 65 + lseg + i] = Kg[(size_t)pt0 * HD_ + lseg + i];
    }
    {
        float4* svr = (float4*)(sV + lrow * 64 + lseg);
        const float4* vr = (const float4*)(Vg + (size_t)pt0 * HD_ + lseg);
        svr[0]=vr[0]; svr[1]=vr[1]; svr[2]=vr[2]; svr[3]=vr[3];
    }
    // states: gmem flat [e][d] -> smem transposed [d][e] (pitch 68)
#pragma unroll 4
    for (int i = 0; i < 16; i++) {
        int idx = tid * 16 + i;
        int e = idx >> 6, dd = idx & 63;
        sSf[dd * 68 + e] = Sfin[idx];
        sSb[dd * 68 + e] = Sbin[idx];
    }
    if (tid < 64){ szf[tid] = zfin[tid]; szb[tid] = zbin[tid]; }
    __syncthreads();

    // ---- Stage 1: P = Q K^T, store weighted A = P * lam^|r-c| ----
    {
        int ty = tid >> 4, tx = tid & 15;
        int r0 = ty * 4, c0 = tx * 4;
        float acc[4][4];
#pragma unroll
        for (int i = 0; i < 4; i++)
#pragma unroll
            for (int jc = 0; jc < 4; jc++) acc[i][jc] = 0.f;

        for (int d = 0; d < 64; d++) {
            float q0 = sQ[(r0+0)*65+d], q1 = sQ[(r0+1)*65+d];
            float q2 = sQ[(r0+2)*65+d], q3 = sQ[(r0+3)*65+d];
            float k0 = sK[(c0+0)*65+d], k1 = sK[(c0+1)*65+d];
            float k2 = sK[(c0+2)*65+d], k3 = sK[(c0+3)*65+d];
            acc[0][0]=fmaf(q0,k0,acc[0][0]); acc[0][1]=fmaf(q0,k1,acc[0][1]);
            acc[0][2]=fmaf(q0,k2,acc[0][2]); acc[0][3]=fmaf(q0,k3,acc[0][3]);
            acc[1][0]=fmaf(q1,k0,acc[1][0]); acc[1][1]=fmaf(q1,k1,acc[1][1]);
            acc[1][2]=fmaf(q1,k2,acc[1][2]); acc[1][3]=fmaf(q1,k3,acc[1][3]);
            acc[2][0]=fmaf(q2,k0,acc[2][0]); acc[2][1]=fmaf(q2,k1,acc[2][1]);
            acc[2][2]=fmaf(q2,k2,acc[2][2]); acc[2][3]=fmaf(q2,k3,acc[2][3]);
            acc[3][0]=fmaf(q3,k0,acc[3][0]); acc[3][1]=fmaf(q3,k1,acc[3][1]);
            acc[3][2]=fmaf(q3,k2,acc[3][2]); acc[3][3]=fmaf(q3,k3,acc[3][3]);
        }
#pragma unroll
        for (int i = 0; i < 4; i++) {
            int r = r0 + i;
#pragma unroll
            for (int jc = 0; jc < 4; jc++) {
                int cc = c0 + jc;
                int dlt = r >= cc ? r - cc : cc - r;
                sP[r * 65 + cc] = acc[i][jc] * slp[dlt];
            }
        }
    }
    __syncthreads();

    // ---- Stage 2: Y = A V + state terms; normalize; write split bf16 ----
    {
        int rr = (tid >> 3) * 2;          // rows rr, rr+1
        int c0 = (tid & 7) * 8;           // 8 cols
        float aA[2][8], aIf[2][8], aIb[2][8];
#pragma unroll
        for (int i = 0; i < 2; i++)
#pragma unroll
            for (int jc = 0; jc < 8; jc++){ aA[i][jc]=0.f; aIf[i][jc]=0.f; aIb[i][jc]=0.f; }
        float cs0 = 0.f, cs1 = 0.f;
        float cqf0 = 0.f, cqf1 = 0.f, cqb0 = 0.f, cqb1 = 0.f;

        for (int s = 0; s < 64; s++) {
            float a0 = sP[rr * 65 + s];
            float a1 = sP[(rr + 1) * 65 + s];
            cs0 += a0; cs1 += a1;
            float4 v0 = *(const float4*)(sV + s * 64 + c0);
            float4 v1 = *(const float4*)(sV + s * 64 + c0 + 4);
            aA[0][0]=fmaf(a0,v0.x,aA[0][0]); aA[0][1]=fmaf(a0,v0.y,aA[0][1]);
            aA[0][2]=fmaf(a0,v0.z,aA[0][2]); aA[0][3]=fmaf(a0,v0.w,aA[0][3]);
            aA[0][4]=fmaf(a0,v1.x,aA[0][4]); aA[0][5]=fmaf(a0,v1.y,aA[0][5]);
            aA[0][6]=fmaf(a0,v1.z,aA[0][6]); aA[0][7]=fmaf(a0,v1.w,aA[0][7]);
            aA[1][0]=fmaf(a1,v0.x,aA[1][0]); aA[1][1]=fmaf(a1,v0.y,aA[1][1]);
            aA[1][2]=fmaf(a1,v0.z,aA[1][2]); aA[1][3]=fmaf(a1,v0.w,aA[1][3]);
            aA[1][4]=fmaf(a1,v1.x,aA[1][4]); aA[1][5]=fmaf(a1,v1.y,aA[1][5]);
            aA[1][6]=fmaf(a1,v1.z,aA[1][6]); aA[1][7]=fmaf(a1,v1.w,aA[1][7]);
        }
        for (int d = 0; d < 64; d++) {
            float q0 = sQ[rr * 65 + d];
            float q1 = sQ[(rr + 1) * 65 + d];
            cqf0 = fmaf(q0, szf[d], cqf0);
            cqf1 = fmaf(q1, szf[d], cqf1);
            cqb0 = fmaf(q0, szb[d], cqb0);
            cqb1 = fmaf(q1, szb[d], cqb1);
            float4 f0 = *(const float4*)(sSf + d * 68 + c0);
            float4 f1 = *(const float4*)(sSf + d * 68 + c0 + 4);
            float4 b0 = *(const float4*)(sSb + d * 68 + c0);
            float4 b1 = *(const float4*)(sSb + d * 68 + c0 + 4);
            aIf[0][0]=fmaf(q0,f0.x,aIf[0][0]); aIf[0][1]=fmaf(q0,f0.y,aIf[0][1]);
            aIf[0][2]=fmaf(q0,f0.z,aIf[0][2]); aIf[0][3]=fmaf(q0,f0.w,aIf[0][3]);
            aIf[0][4]=fmaf(q0,f1.x,aIf[0][4]); aIf[0][5]=fmaf(q0,f1.y,aIf[0][5]);
            aIf[0][6]=fmaf(q0,f1.z,aIf[0][6]); aIf[0][7]=fmaf(q0,f1.w,aIf[0][7]);
            aIf[1][0]=fmaf(q1,f0.x,aIf[1][0]); aIf[1][1]=fmaf(q1,f0.y,aIf[1][1]);
            aIf[1][2]=fmaf(q1,f0.z,aIf[1][2]); aIf[1][3]=fmaf(q1,f0.w,aIf[1][3]);
            aIf[1][4]=fmaf(q1,f1.x,aIf[1][4]); aIf[1][5]=fmaf(q1,f1.y,aIf[1][5]);
            aIf[1][6]=fmaf(q1,f1.z,aIf[1][6]); aIf[1][7]=fmaf(q1,f1.w,aIf[1][7]);
            aIb[0][0]=fmaf(q0,b0.x,aIb[0][0]); aIb[0][1]=fmaf(q0,b0.y,aIb[0][1]);
            aIb[0][2]=fmaf(q0,b0.z,aIb[0][2]); aIb[0][3]=fmaf(q0,b0.w,aIb[0][3]);
            aIb[0][4]=fmaf(q0,b1.x,aIb[0][4]); aIb[0][5]=fmaf(q0,b1.y,aIb[0][5]);
            aIb[0][6]=fmaf(q0,b1.z,aIb[0][6]); aIb[0][7]=fmaf(q0,b1.w,aIb[0][7]);
            aIb[1][0]=fmaf(q1,b0.x,aIb[1][0]); aIb[1][1]=fmaf(q1,b0.y,aIb[1][1]);
            aIb[1][2]=fmaf(q1,b0.z,aIb[1][2]); aIb[1][3]=fmaf(q1,b0.w,aIb[1][3]);
            aIb[1][4]=fmaf(q1,b1.x,aIb[1][4]); aIb[1][5]=fmaf(q1,b1.y,aIb[1][5]);
            aIb[1][6]=fmaf(q1,b1.z,aIb[1][6]); aIb[1][7]=fmaf(q1,b1.w,aIb[1][7]);
        }

        int b = bh >> 3;
#pragma unroll
        for (int i = 0; i < 2; i++) {
            int r = rr + i;
            int t = j * CH_ + r;
            float lf = slp[r + 1];
            float lb = slp[CH_ - r];
            float cden = (i ? cs1 : cs0)
                       + lf * (i ? cqf1 : cqf0)
                       + lb * (i ? cqb1 : cqb0);
            float inv = 1.f / fmaxf(cden, 1e-6f);
            uint32_t hp[4], lp[4];
#pragma unroll
            for (int u = 0; u < 4; u++){
                float y0 = (aA[i][2*u]   + lf*aIf[i][2*u]   + lb*aIb[i][2*u]  ) * inv;
                float y1 = (aA[i][2*u+1] + lf*aIf[i][2*u+1] + lb*aIb[i][2*u+1]) * inv;
                __nv_bfloat16 h0 = __float2bfloat16(y0), h1 = __float2bfloat16(y1);
                float l0 = y0 - __bfloat162float(h0);
                float l1 = y1 - __bfloat162float(h1);
                hp[u] = (uint32_t)__bfloat16_as_ushort(h0) |
                        ((uint32_t)__bfloat16_as_ushort(h1) << 16);
                lp[u] = (uint32_t)__bfloat16_as_ushort(__float2bfloat16(l0)) |
                        ((uint32_t)__bfloat16_as_ushort(__float2bfloat16(l1)) << 16);
            }
            size_t dst = ((size_t)(b * T_ + t) * D_) + h * HD_ + c0;
            *(uint4*)(g_ath + dst) = make_uint4(hp[0], hp[1], hp[2], hp[3]);
            *(uint4*)(g_atl + dst) = make_uint4(lp[0], lp[1], lp[2], lp[3]);
        }
    }
}

// ------------------------- launcher ----------------------------------------
extern "C" void kernel_launch(void* const* d_in, const int* in_sizes, int n_in,
                              void* d_out, int out_size)
{
    const float* x    = (const float*)d_in[0];
    const float* Wq   = (const float*)d_in[2];
    const float* Wk   = (const float*)d_in[3];
    const float* Wv   = (const float*)d_in[4];
    const float* Wo   = (const float*)d_in[5];
    const float* bo   = (const float*)d_in[6];
    const float* g1   = (const float*)d_in[7];
    const float* b1   = (const float*)d_in[8];
    const float* g2   = (const float*)d_in[9];
    const float* b2   = (const float*)d_in[10];
    const float* W1   = (const float*)d_in[11];
    const float* bf1  = (const float*)d_in[12];
    const float* W2   = (const float*)d_in[13];
    const float* bf2  = (const float*)d_in[14];
    const float* dlog = (const float*)d_in[15];
    float* out = (float*)d_out;

#define SYM(p, s) cudaGetSymbolAddress((void**)&p, s)
    __nv_bfloat16 *xnh,*xnl,*ath,*atl,*h2h,*h2l,*f1h,*f1l;
    __nv_bfloat16 *wqkvh,*wqkvl,*woh,*wol,*w1h,*w1l,*w2h,*w2l;
    float *QKV,*x2;
    SYM(xnh,g_xnh); SYM(xnl,g_xnl); SYM(ath,g_ath); SYM(atl,g_atl);
    SYM(h2h,g_h2h); SYM(h2l,g_h2l); SYM(f1h,g_f1h); SYM(f1l,g_f1l);
    SYM(wqkvh,g_wqkvh); SYM(wqkvl,g_wqkvl);
    SYM(woh,g_woh); SYM(wol,g_wol);
    SYM(w1h,g_w1h); SYM(w1l,g_w1l); SYM(w2h,g_w2h); SYM(w2l,g_w2l);
    SYM(QKV,g_QKV); SYM(x2,g_x2);
#undef SYM

    cudaFuncSetAttribute(tc_gemm<4,512>,   cudaFuncAttributeMaxDynamicSharedMemorySize, GEMM_SMEM);
    cudaFuncSetAttribute(tc_gemm<3,512>,   cudaFuncAttributeMaxDynamicSharedMemorySize, GEMM_SMEM);
    cudaFuncSetAttribute(tc_gemm64<512>,   cudaFuncAttributeMaxDynamicSharedMemorySize, GEMM64_SMEM);
    cudaFuncSetAttribute(tc_gemm64<2048>,  cudaFuncAttributeMaxDynamicSharedMemorySize, GEMM64_SMEM);
    cudaFuncSetAttribute(chunk_comb_kernel,cudaFuncAttributeMaxDynamicSharedMemorySize, CC_SMEM_BYTES);

    dim3 blk(256);
    dim3 gQKV((3*D_) / 128, M_ / 128);  // (12, 32) = 384 CTAs
    dim3 gD64(D_ / 128, M_ / 64);       // (4, 64)  = 256 CTAs
    dim3 gF(F_ / 128, M_ / 128);        // (16, 32) = 512 CTAs

    // 0) all weight splits, one launch
    split_all_kernel<<<3145728/256, blk>>>(Wq, Wk, Wv, Wo, W1, W2);
    // 1) LN1 (+split)
    ln_split_kernel<<<M_, blk>>>(x, g1, b1, xnh, xnl);
    // 2) fused Q/K/V projection — one launch, 128x128 tiles, 384 CTAs
    tc_gemm<4,512><<<gQKV, blk, GEMM_SMEM>>>(xnh, xnl, wqkvh, wqkvl, 3*D_,
                                             nullptr, QKV, nullptr, nullptr);
    // 3) dual-direction two-level scan + fused chunk/combine
    usum_dual_kernel<<<NBH_ * NCH_, blk>>>(dlog);            // 512 blocks
    sweep_kernel<<<2 * NBH_ * 16, blk>>>(dlog);              // 512 blocks
    chunk_comb_kernel<<<NBH_ * NCH_, blk, CC_SMEM_BYTES>>>(dlog);  // 512 blocks
    // 4) Wo + bias + residual -> fp32 x2   (64-row tiles, 256 CTAs)
    tc_gemm64<512><<<gD64, blk, GEMM64_SMEM>>>(ath, atl, woh, wol, D_, bo, x, x2);
    // 5) LN2 (+split)
    ln_split_kernel<<<M_, blk>>>(x2, g2, b2, h2h, h2l);
    // 6) FFN up + GELU -> split bf16
    tc_gemm<3,512><<<gF, blk, GEMM_SMEM>>>(h2h, h2l, w1h, w1l, F_, bf1, nullptr, f1h, f1l);
    // 7) FFN down + bias + residual -> final output (64-row tiles, 256 CTAs)
    tc_gemm64<2048><<<gD64, blk, GEMM64_SMEM>>>(f1h, f1l, w2h, w2l, D_, bf2, x2, out);
}

// round 13
// speedup vs baseline: 1.5524x; 1.2718x over previous
#include <cuda_runtime.h>
#include <cuda_fp16.h>
#include <math.h>
#include <stdint.h>

#define B_   2
#define T_   2048
#define D_   512
#define H_   8
#define HD_  64
#define F_   2048
#define M_   (B_*T_)
#define CH_  64
#define NCH_ (T_/CH_)
#define NBH_ (B_*H_)
#define QKVO (NBH_*T_*HD_)

// ------------------------- scratch globals ---------------------------------
__device__ __half g_xnh[M_*D_], g_xnl[M_*D_];
__device__ __half g_ath[M_*D_], g_atl[M_*D_];
__device__ __half g_h2h[M_*D_], g_h2l[M_*D_];
__device__ __half g_f1h[M_*F_], g_f1l[M_*F_];
__device__ __half g_wqkvh[3*D_*D_];          // Wq|Wk|Wv rows (hi only)
__device__ __half g_woh[D_*D_];
__device__ __half g_w1h[F_*D_];
__device__ __half g_w2h[D_*F_];
__device__ float g_QKV[3*QKVO];              // Q|K|V [b,h,t,e]
__device__ float g_x2[M_*D_];
__device__ float g_Schk[2*NBH_*NCH_*HD_*HD_];
__device__ float g_zchk[2*NBH_*NCH_*HD_];
__device__ float g_U   [2*NBH_*NCH_*HD_*HD_];
__device__ float g_zU  [2*NBH_*NCH_*HD_];

// ------------------------- helpers -----------------------------------------
static __device__ __forceinline__ uint32_t stou(const void* p){
    uint32_t a;
    asm("{ .reg .u64 t; cvta.to.shared.u64 t, %1; cvt.u32.u64 %0, t; }" : "=r"(a) : "l"(p));
    return a;
}
static __device__ __forceinline__ void cp16(uint32_t dst, const void* src){
    asm volatile("cp.async.cg.shared.global [%0], [%1], 16;" :: "r"(dst), "l"(src));
}
static __device__ __forceinline__ void ldmA(uint32_t* a, uint32_t addr){
    asm volatile("ldmatrix.sync.aligned.m8n8.x4.shared.b16 {%0,%1,%2,%3}, [%4];"
        : "=r"(a[0]),"=r"(a[1]),"=r"(a[2]),"=r"(a[3]) : "r"(addr));
}
static __device__ __forceinline__ void ldmB(uint32_t* b, uint32_t addr){
    asm volatile("ldmatrix.sync.aligned.m8n8.x2.shared.b16 {%0,%1}, [%2];"
        : "=r"(b[0]),"=r"(b[1]) : "r"(addr));
}
static __device__ __forceinline__ void mma16816(float* c, const uint32_t* a, const uint32_t* b){
    asm volatile("mma.sync.aligned.m16n8k16.row.col.f32.f16.f16.f32 "
        "{%0,%1,%2,%3}, {%4,%5,%6,%7}, {%8,%9}, {%0,%1,%2,%3};"
        : "+f"(c[0]),"+f"(c[1]),"+f"(c[2]),"+f"(c[3])
        : "r"(a[0]),"r"(a[1]),"r"(a[2]),"r"(a[3]), "r"(b[0]),"r"(b[1]));
}
static __device__ __forceinline__ uint32_t pack2h(float a, float b, float* la, float* lb){
    __half ha = __float2half(a), hb = __float2half(b);
    *la = a - __half2float(ha);
    *lb = b - __half2float(hb);
    return (uint32_t)__half_as_ushort(ha) | ((uint32_t)__half_as_ushort(hb) << 16);
}
static __device__ __forceinline__ uint32_t pack2l(float la, float lb){
    return (uint32_t)__half_as_ushort(__float2half(la)) |
           ((uint32_t)__half_as_ushort(__float2half(lb)) << 16);
}

#define ROWB  144
#define ATILE 18432
#define STGB  36864
#define GEMM_SMEM (2*STGB)
#define BOFF64  9216
#define STGB64  27648
#define GEMM64_SMEM (2*STGB64)

// ---------------------------------------------------------------------------
// 128x128 split-fp16 GEMM (K'=2K: passes (Ah,Bh),(Al,Bh)), 2-stage.
// MODE: 3=bias+gelu->split fp16   4=fused QKV scatter (elu for n<1024)
// ---------------------------------------------------------------------------
template<int MODE, int KDIM>
__global__ void __launch_bounds__(256,2) tc_gemm(
    const __half* __restrict__ Ah, const __half* __restrict__ Al,
    const __half* __restrict__ Bh,
    int N, const float* __restrict__ bias,
    float* __restrict__ outF,
    __half* __restrict__ outH, __half* __restrict__ outL)
{
    extern __shared__ char dyns[];
    uint32_t sb = stou(dyns);

    int tid = threadIdx.x;
    int lane = tid & 31, w = tid >> 5;
    int warp_m = w >> 2, warp_n = w & 3;
    int m0 = blockIdx.y * 128;
    int n0 = blockIdx.x * 128;

    float acc[4][4][4];
#pragma unroll
    for (int i=0;i<4;i++)
#pragma unroll
        for (int j=0;j<4;j++)
#pragma unroll
            for (int k=0;k<4;k++) acc[i][j][k] = 0.f;

    const int NIT = 2*KDIM/64;

    auto fill = [&](int itf){
        int st = itf & 1;
        int kp = itf * 64;
        int pass = kp / KDIM;
        int koff = kp - pass*KDIM;
        const __half* pA = pass ? Al : Ah;
        uint32_t base = sb + st*STGB;
#pragma unroll
        for (int i=0;i<8;i++){
            int q = tid + i*256;
            int isB = q >> 10;
            int r   = (q >> 3) & 127;
            int c16 = q & 7;
            const __half* src =
                (isB ? (Bh + (size_t)(n0+r)*KDIM) : (pA + (size_t)(m0+r)*KDIM)) + koff + c16*8;
            cp16(base + isB*ATILE + r*ROWB + c16*16, src);
        }
        asm volatile("cp.async.commit_group;" ::: "memory");
    };

    uint32_t aBase = (uint32_t)((warp_m*64 + (lane & 15))*ROWB + ((lane >> 4) << 4));
    uint32_t bBase = (uint32_t)(ATILE + (warp_n*32 + (lane & 7))*ROWB + (((lane >> 3) & 1) << 4));

    fill(0);
    for (int it=0; it<NIT; ++it){
        if (it+1 < NIT){
            fill(it+1);
            asm volatile("cp.async.wait_group 1;" ::: "memory");
        } else {
            asm volatile("cp.async.wait_group 0;" ::: "memory");
        }
        __syncthreads();
        uint32_t stg = sb + (it&1)*STGB;
#pragma unroll
        for (int kk=0; kk<64; kk+=16){
            uint32_t afrag[4][4], bfrag[4][2];
#pragma unroll
            for (int mt=0;mt<4;mt++) ldmA(afrag[mt], stg + aBase + mt*(16*ROWB) + kk*2);
#pragma unroll
            for (int nt=0;nt<4;nt++) ldmB(bfrag[nt], stg + bBase + nt*(8*ROWB) + kk*2);
#pragma unroll
            for (int mt=0;mt<4;mt++)
#pragma unroll
                for (int nt=0;nt<4;nt++) mma16816(acc[mt][nt], afrag[mt], bfrag[nt]);
        }
        __syncthreads();
    }

    int mb = m0 + warp_m*64;
    int nb = n0 + warp_n*32;
#pragma unroll
    for (int mt=0; mt<4; mt++){
#pragma unroll
        for (int half=0; half<2; half++){
            int m = mb + mt*16 + (lane>>2) + half*8;
            int bb = m >> 11, tt = m & (T_-1);
#pragma unroll
            for (int nt=0; nt<4; nt++){
                int n = nb + nt*8 + (lane&3)*2;
                float v0 = acc[mt][nt][half*2];
                float v1 = acc[mt][nt][half*2+1];
                if (MODE == 4){
                    int mat = n >> 9;              // 0=Q 1=K 2=V
                    if (mat < 2){
                        v0 = v0>0.f ? v0+1.f : expf(v0);
                        v1 = v1>0.f ? v1+1.f : expf(v1);
                    }
                    int hh = (n >> 6) & 7, ee = n & 63;
                    float* dst = outF + (size_t)mat*QKVO
                               + ((((size_t)(bb*H_ + hh))*T_ + tt)<<6) + ee;
                    float2 o; o.x=v0; o.y=v1;
                    *(float2*)dst = o;
                } else {   // MODE 3: bias + exact GELU -> split fp16
                    size_t idx = (size_t)m*N + n;
                    float a = v0 + bias[n];
                    float b = v1 + bias[n+1];
                    a = 0.5f*a*(1.f+erff(a*0.70710678118654752f));
                    b = 0.5f*b*(1.f+erff(b*0.70710678118654752f));
                    float la, lb;
                    uint32_t hp = pack2h(a, b, &la, &lb);
                    uint32_t lp = pack2l(la, lb);
                    *(uint32_t*)(outH + idx) = hp;
                    *(uint32_t*)(outL + idx) = lp;
                }
            }
        }
    }
}

// ---------------------------------------------------------------------------
// 64x128 split-fp16 GEMM, 2-stage, 3 CTAs/SM. bias+res -> fp32.
// ---------------------------------------------------------------------------
template<int KDIM>
__global__ void __launch_bounds__(256,3) tc_gemm64(
    const __half* __restrict__ Ah, const __half* __restrict__ Al,
    const __half* __restrict__ Bh,
    int N, const float* __restrict__ bias, const float* __restrict__ res,
    float* __restrict__ outF)
{
    extern __shared__ char dyns[];
    uint32_t sb = stou(dyns);

    int tid = threadIdx.x;
    int lane = tid & 31, w = tid >> 5;
    int warp_m = w >> 2, warp_n = w & 3;
    int m0 = blockIdx.y * 64;
    int n0 = blockIdx.x * 128;

    float acc[2][4][4];
#pragma unroll
    for (int i=0;i<2;i++)
#pragma unroll
        for (int j=0;j<4;j++)
#pragma unroll
            for (int k=0;k<4;k++) acc[i][j][k] = 0.f;

    const int NIT = 2*KDIM/64;

    auto fill = [&](int itf){
        int st = itf & 1;
        int kp = itf * 64;
        int pass = kp / KDIM;
        int koff = kp - pass*KDIM;
        const __half* pA = pass ? Al : Ah;
        uint32_t base = sb + st*STGB64;
#pragma unroll
        for (int i=0;i<6;i++){
            int q = tid + i*256;
            if (q < 512){
                int r = q >> 3, c16 = q & 7;
                cp16(base + r*ROWB + c16*16,
                     pA + (size_t)(m0+r)*KDIM + koff + c16*8);
            } else {
                int q2 = q - 512;
                int r = q2 >> 3, c16 = q2 & 7;
                cp16(base + BOFF64 + r*ROWB + c16*16,
                     Bh + (size_t)(n0+r)*KDIM + koff + c16*8);
            }
        }
        asm volatile("cp.async.commit_group;" ::: "memory");
    };

    uint32_t aBase = (uint32_t)((warp_m*32 + (lane & 15))*ROWB + ((lane >> 4) << 4));
    uint32_t bBase = (uint32_t)(BOFF64 + (warp_n*32 + (lane & 7))*ROWB + (((lane >> 3) & 1) << 4));

    fill(0);
    for (int it=0; it<NIT; ++it){
        if (it+1 < NIT){
            fill(it+1);
            asm volatile("cp.async.wait_group 1;" ::: "memory");
        } else {
            asm volatile("cp.async.wait_group 0;" ::: "memory");
        }
        __syncthreads();
        uint32_t stg = sb + (it&1)*STGB64;
#pragma unroll
        for (int kk=0; kk<64; kk+=16){
            uint32_t afrag[2][4], bfrag[4][2];
#pragma unroll
            for (int mt=0;mt<2;mt++) ldmA(afrag[mt], stg + aBase + mt*(16*ROWB) + kk*2);
#pragma unroll
            for (int nt=0;nt<4;nt++) ldmB(bfrag[nt], stg + bBase + nt*(8*ROWB) + kk*2);
#pragma unroll
            for (int mt=0;mt<2;mt++)
#pragma unroll
                for (int nt=0;nt<4;nt++) mma16816(acc[mt][nt], afrag[mt], bfrag[nt]);
        }
        __syncthreads();
    }

    int mb = m0 + warp_m*32;
    int nb = n0 + warp_n*32;
#pragma unroll
    for (int mt=0; mt<2; mt++){
#pragma unroll
        for (int half=0; half<2; half++){
            int m = mb + mt*16 + (lane>>2) + half*8;
#pragma unroll
            for (int nt=0; nt<4; nt++){
                int n = nb + nt*8 + (lane&3)*2;
                float v0 = acc[mt][nt][half*2];
                float v1 = acc[mt][nt][half*2+1];
                size_t idx = (size_t)m*N + n;
                float2 rv = *(const float2*)(res + idx);
                float2 o;
                o.x = v0 + bias[n]   + rv.x;
                o.y = v1 + bias[n+1] + rv.y;
                *(float2*)(outF + idx) = o;
            }
        }
    }
}

// ------------------------- batched weight split (hi only, vectorized) -------
// groups of 4 floats: qkv 196608 | wo 65536 | w1 262144 | w2 262144 = 786432
__global__ void __launch_bounds__(256) split_all_kernel(
    const float* __restrict__ Wq, const float* __restrict__ Wk,
    const float* __restrict__ Wv, const float* __restrict__ Wo,
    const float* __restrict__ W1, const float* __restrict__ W2)
{
    int g = blockIdx.x * 256 + threadIdx.x;
    const float* src; __half* dh;
    if (g < 196608){
        int which = g >> 16;            // 65536 groups per matrix
        int j = g & 65535;
        src = (which==0 ? Wq : which==1 ? Wk : Wv) + j*4;
        dh = g_wqkvh + ((size_t)which << 18) + j*4;
    } else if (g < 262144){
        int j = g - 196608; src = Wo + (size_t)j*4; dh = g_woh + (size_t)j*4;
    } else if (g < 524288){
        int j = g - 262144; src = W1 + (size_t)j*4; dh = g_w1h + (size_t)j*4;
    } else {
        int j = g - 524288; src = W2 + (size_t)j*4; dh = g_w2h + (size_t)j*4;
    }
    float4 v = *(const float4*)src;
    uint2 hp;
    hp.x = (uint32_t)__half_as_ushort(__float2half(v.x)) |
           ((uint32_t)__half_as_ushort(__float2half(v.y)) << 16);
    hp.y = (uint32_t)__half_as_ushort(__float2half(v.z)) |
           ((uint32_t)__half_as_ushort(__float2half(v.w)) << 16);
    *(uint2*)dh = hp;
}

// ------------------------- LayerNorm + fp16 split ---------------------------
__global__ void __launch_bounds__(256) ln_split_kernel(
    const float* __restrict__ x, const float* __restrict__ g,
    const float* __restrict__ b, __half* __restrict__ yh,
    __half* __restrict__ yl)
{
    int row = blockIdx.x;
    const float* xr = x + (size_t)row * D_;
    int tid = threadIdx.x;
    float v0 = xr[tid], v1 = xr[tid + 256];
    float s  = v0 + v1, ss = v0*v0 + v1*v1;
    __shared__ float sh[16];
#pragma unroll
    for (int o = 16; o; o >>= 1) {
        s  += __shfl_xor_sync(0xffffffffu, s,  o);
        ss += __shfl_xor_sync(0xffffffffu, ss, o);
    }
    int w = tid >> 5;
    if ((tid & 31) == 0) { sh[w] = s; sh[w + 8] = ss; }
    __syncthreads();
    float S = 0.f, SS = 0.f;
#pragma unroll
    for (int i = 0; i < 8; i++) { S += sh[i]; SS += sh[8 + i]; }
    float mean = S * (1.0f / D_);
    float rstd = rsqrtf(SS * (1.0f / D_) - mean*mean + 1e-5f);
    size_t base = (size_t)row * D_;
    float o0 = (v0 - mean) * rstd * g[tid]       + b[tid];
    float o1 = (v1 - mean) * rstd * g[tid + 256] + b[tid + 256];
    __half h0 = __float2half(o0), h1 = __float2half(o1);
    yh[base + tid]       = h0;
    yh[base + tid + 256] = h1;
    yl[base + tid]       = __float2half(o0 - __half2float(h0));
    yl[base + tid + 256] = __float2half(o1 - __half2float(h1));
}

// ---------------------------------------------------------------------------
// Scan level 1 (DUAL direction) — validated R12, unchanged
// ---------------------------------------------------------------------------
__global__ void __launch_bounds__(256) usum_dual_kernel(const float* __restrict__ dlogit)
{
    int bx  = blockIdx.x;
    int j   = bx & 31;
    int bh  = bx >> 5;
    int h   = bh & 7;
    float lam = 1.f / (1.f + expf(-dlogit[h]));

    __shared__ float sK[CH_ * HD_];
    __shared__ float sV[CH_ * HD_];
    __shared__ float wf[CH_], wb[CH_];

    int tid = threadIdx.x;
    if (tid < CH_){
        wf[tid] = powf(lam, (float)(CH_ - 1 - tid));
        wb[tid] = powf(lam, (float)tid);
    }

    int lrow = tid >> 2;
    int lseg = (tid & 3) * 16;
    int pt = j * CH_ + lrow;
    const float* Kg = g_QKV + QKVO     + (size_t)bh * T_ * HD_;
    const float* Vg = g_QKV + 2*QKVO   + (size_t)bh * T_ * HD_;
    {
        const float4* kr = (const float4*)(Kg + (size_t)pt * HD_ + lseg);
        const float4* vr = (const float4*)(Vg + (size_t)pt * HD_ + lseg);
        float4* sk = (float4*)(sK + lrow * HD_ + lseg);
        float4* sv = (float4*)(sV + lrow * HD_ + lseg);
        sk[0]=kr[0]; sk[1]=kr[1]; sk[2]=kr[2]; sk[3]=kr[3];
        sv[0]=vr[0]; sv[1]=vr[1]; sv[2]=vr[2]; sv[3]=vr[3];
    }
    __syncthreads();

    int d = tid & 63, c = tid >> 6;
    int e0 = c * 16;
    float aF[16], aB[16];
#pragma unroll
    for (int i = 0; i < 16; i++){ aF[i] = 0.f; aB[i] = 0.f; }
    float zF = 0.f, zB = 0.f;

#pragma unroll 4
    for (int s = 0; s < CH_; s++){
        float kr = sK[s * HD_ + d];
        float kf = kr * wf[s];
        float kb = kr * wb[s];
        zF += kf; zB += kb;
        const float4* vv = (const float4*)(sV + s * HD_ + e0);
        float4 a0 = vv[0], a1 = vv[1], a2 = vv[2], a3 = vv[3];
        aF[0]=fmaf(kf,a0.x,aF[0]); aB[0]=fmaf(kb,a0.x,aB[0]);
        aF[1]=fmaf(kf,a0.y,aF[1]); aB[1]=fmaf(kb,a0.y,aB[1]);
        aF[2]=fmaf(kf,a0.z,aF[2]); aB[2]=fmaf(kb,a0.z,aB[2]);
        aF[3]=fmaf(kf,a0.w,aF[3]); aB[3]=fmaf(kb,a0.w,aB[3]);
        aF[4]=fmaf(kf,a1.x,aF[4]); aB[4]=fmaf(kb,a1.x,aB[4]);
        aF[5]=fmaf(kf,a1.y,aF[5]); aB[5]=fmaf(kb,a1.y,aB[5]);
        aF[6]=fmaf(kf,a1.z,aF[6]); aB[6]=fmaf(kb,a1.z,aB[6]);
        aF[7]=fmaf(kf,a1.w,aF[7]); aB[7]=fmaf(kb,a1.w,aB[7]);
        aF[8]=fmaf(kf,a2.x,aF[8]); aB[8]=fmaf(kb,a2.x,aB[8]);
        aF[9]=fmaf(kf,a2.y,aF[9]); aB[9]=fmaf(kb,a2.y,aB[9]);
        aF[10]=fmaf(kf,a2.z,aF[10]); aB[10]=fmaf(kb,a2.z,aB[10]);
        aF[11]=fmaf(kf,a2.w,aF[11]); aB[11]=fmaf(kb,a2.w,aB[11]);
        aF[12]=fmaf(kf,a3.x,aF[12]); aB[12]=fmaf(kb,a3.x,aB[12]);
        aF[13]=fmaf(kf,a3.y,aF[13]); aB[13]=fmaf(kb,a3.y,aB[13]);
        aF[14]=fmaf(kf,a3.z,aF[14]); aB[14]=fmaf(kb,a3.z,aB[14]);
        aF[15]=fmaf(kf,a3.w,aF[15]); aB[15]=fmaf(kb,a3.w,aB[15]);
    }

    float* Uf = g_U + (size_t)((0 * NBH_ + bh) * NCH_ + j) * (HD_ * HD_);
    float* Ub = g_U + (size_t)((1 * NBH_ + bh) * NCH_ + (NCH_ - 1 - j)) * (HD_ * HD_);
#pragma unroll
    for (int i = 0; i < 16; i++){
        Uf[(e0 + i) * 64 + d] = aF[i];
        Ub[(e0 + i) * 64 + d] = aB[i];
    }
    if (c == 0){
        g_zU[(size_t)((0 * NBH_ + bh) * NCH_ + j) * HD_ + d] = zF;
        g_zU[(size_t)((1 * NBH_ + bh) * NCH_ + (NCH_ - 1 - j)) * HD_ + d] = zB;
    }
}

// ---------------------------------------------------------------------------
// Scan level 2: sweep — validated, unchanged
// ---------------------------------------------------------------------------
__global__ void __launch_bounds__(256) sweep_kernel(const float* __restrict__ dlogit)
{
    int bx  = blockIdx.x;
    int seg = bx & 15;
    int bh  = (bx >> 4) & 15;
    int dir = bx >> 8;
    int h   = bh & 7;
    float lam  = 1.f / (1.f + expf(-dlogit[h]));
    float lamC = powf(lam, (float)CH_);

    int el = seg * 256 + threadIdx.x;
    size_t base = (size_t)((dir * NBH_ + bh) * NCH_) * (HD_ * HD_);
    float S = 0.f;
#pragma unroll
    for (int jj = 0; jj < NCH_; jj++){
        size_t o = base + (size_t)jj * (HD_ * HD_) + el;
        float u = g_U[o];
        g_Schk[o] = S;
        S = fmaf(lamC, S, u);
    }
    if (seg == 0 && threadIdx.x < HD_){
        int d = threadIdx.x;
        size_t zb = (size_t)((dir * NBH_ + bh) * NCH_) * HD_;
        float z = 0.f;
#pragma unroll
        for (int jj = 0; jj < NCH_; jj++){
            float zu = g_zU[zb + jj * HD_ + d];
            g_zchk[zb + jj * HD_ + d] = z;
            z = fmaf(lamC, z, zu);
        }
    }
}

// ---------------------------------------------------------------------------
// Combined dual-direction chunk kernel + normalize + split-fp16 output.
// (validated R12; only output packing changed to fp16)
// ---------------------------------------------------------------------------
#define COFF_Q   0
#define COFF_K   4160
#define COFF_P   8320
#define COFF_V   12480
#define COFF_SF  16576
#define COFF_SB  20928
#define COFF_ZF  25280
#define COFF_ZB  25344
#define COFF_LP  25408
#define CC_SMEM_BYTES ((25408 + 80) * 4)

__global__ void __launch_bounds__(256) chunk_comb_kernel(const float* __restrict__ dlogit)
{
    extern __shared__ float sm[];
    float* sQ  = sm + COFF_Q;
    float* sK  = sm + COFF_K;
    float* sP  = sm + COFF_P;
    float* sV  = sm + COFF_V;
    float* sSf = sm + COFF_SF;
    float* sSb = sm + COFF_SB;
    float* szf = sm + COFF_ZF;
    float* szb = sm + COFF_ZB;
    float* slp = sm + COFF_LP;

    int bx  = blockIdx.x;
    int j   = bx & 31;
    int bh  = bx >> 5;
    int h   = bh & 7;
    float lam = 1.f / (1.f + expf(-dlogit[h]));

    int tid = threadIdx.x;
    if (tid <= CH_) slp[tid] = powf(lam, (float)tid);

    const float* Qg  = g_QKV            + (size_t)bh * T_ * HD_;
    const float* Kg  = g_QKV + QKVO     + (size_t)bh * T_ * HD_;
    const float* Vg  = g_QKV + 2*QKVO   + (size_t)bh * T_ * HD_;
    const float* Sfin = g_Schk + (size_t)((0 * NBH_ + bh) * NCH_ + j) * (HD_ * HD_);
    const float* Sbin = g_Schk + (size_t)((1 * NBH_ + bh) * NCH_ + (NCH_ - 1 - j)) * (HD_ * HD_);
    const float* zfin = g_zchk + (size_t)((0 * NBH_ + bh) * NCH_ + j) * HD_;
    const float* zbin = g_zchk + (size_t)((1 * NBH_ + bh) * NCH_ + (NCH_ - 1 - j)) * HD_;

    int lrow = tid >> 2;
    int lseg = (tid & 3) * 16;
    int pt0 = j * CH_ + lrow;

#pragma unroll 4
    for (int i = 0; i < 16; i++) {
        sQ[lrow * 65 + lseg + i] = Qg[(size_t)pt0 * HD_ + lseg + i];
        sK[lrow * 65 + lseg + i] = Kg[(size_t)pt0 * HD_ + lseg + i];
    }
    {
        float4* svr = (float4*)(sV + lrow * 64 + lseg);
        const float4* vr = (const float4*)(Vg + (size_t)pt0 * HD_ + lseg);
        svr[0]=vr[0]; svr[1]=vr[1]; svr[2]=vr[2]; svr[3]=vr[3];
    }
#pragma unroll 4
    for (int i = 0; i < 16; i++) {
        int idx = tid * 16 + i;
        int e = idx >> 6, dd = idx & 63;
        sSf[dd * 68 + e] = Sfin[idx];
        sSb[dd * 68 + e] = Sbin[idx];
    }
    if (tid < 64){ szf[tid] = zfin[tid]; szb[tid] = zbin[tid]; }
    __syncthreads();

    {
        int ty = tid >> 4, tx = tid & 15;
        int r0 = ty * 4, c0 = tx * 4;
        float acc[4][4];
#pragma unroll
        for (int i = 0; i < 4; i++)
#pragma unroll
            for (int jc = 0; jc < 4; jc++) acc[i][jc] = 0.f;

        for (int d = 0; d < 64; d++) {
            float q0 = sQ[(r0+0)*65+d], q1 = sQ[(r0+1)*65+d];
            float q2 = sQ[(r0+2)*65+d], q3 = sQ[(r0+3)*65+d];
            float k0 = sK[(c0+0)*65+d], k1 = sK[(c0+1)*65+d];
            float k2 = sK[(c0+2)*65+d], k3 = sK[(c0+3)*65+d];
            acc[0][0]=fmaf(q0,k0,acc[0][0]); acc[0][1]=fmaf(q0,k1,acc[0][1]);
            acc[0][2]=fmaf(q0,k2,acc[0][2]); acc[0][3]=fmaf(q0,k3,acc[0][3]);
            acc[1][0]=fmaf(q1,k0,acc[1][0]); acc[1][1]=fmaf(q1,k1,acc[1][1]);
            acc[1][2]=fmaf(q1,k2,acc[1][2]); acc[1][3]=fmaf(q1,k3,acc[1][3]);
            acc[2][0]=fmaf(q2,k0,acc[2][0]); acc[2][1]=fmaf(q2,k1,acc[2][1]);
            acc[2][2]=fmaf(q2,k2,acc[2][2]); acc[2][3]=fmaf(q2,k3,acc[2][3]);
            acc[3][0]=fmaf(q3,k0,acc[3][0]); acc[3][1]=fmaf(q3,k1,acc[3][1]);
            acc[3][2]=fmaf(q3,k2,acc[3][2]); acc[3][3]=fmaf(q3,k3,acc[3][3]);
        }
#pragma unroll
        for (int i = 0; i < 4; i++) {
            int r = r0 + i;
#pragma unroll
            for (int jc = 0; jc < 4; jc++) {
                int cc = c0 + jc;
                int dlt = r >= cc ? r - cc : cc - r;
                sP[r * 65 + cc] = acc[i][jc] * slp[dlt];
            }
        }
    }
    __syncthreads();

    {
        int rr = (tid >> 3) * 2;
        int c0 = (tid & 7) * 8;
        float aA[2][8], aIf[2][8], aIb[2][8];
#pragma unroll
        for (int i = 0; i < 2; i++)
#pragma unroll
            for (int jc = 0; jc < 8; jc++){ aA[i][jc]=0.f; aIf[i][jc]=0.f; aIb[i][jc]=0.f; }
        float cs0 = 0.f, cs1 = 0.f;
        float cqf0 = 0.f, cqf1 = 0.f, cqb0 = 0.f, cqb1 = 0.f;

        for (int s = 0; s < 64; s++) {
            float a0 = sP[rr * 65 + s];
            float a1 = sP[(rr + 1) * 65 + s];
            cs0 += a0; cs1 += a1;
            float4 v0 = *(const float4*)(sV + s * 64 + c0);
            float4 v1 = *(const float4*)(sV + s * 64 + c0 + 4);
            aA[0][0]=fmaf(a0,v0.x,aA[0][0]); aA[0][1]=fmaf(a0,v0.y,aA[0][1]);
            aA[0][2]=fmaf(a0,v0.z,aA[0][2]); aA[0][3]=fmaf(a0,v0.w,aA[0][3]);
            aA[0][4]=fmaf(a0,v1.x,aA[0][4]); aA[0][5]=fmaf(a0,v1.y,aA[0][5]);
            aA[0][6]=fmaf(a0,v1.z,aA[0][6]); aA[0][7]=fmaf(a0,v1.w,aA[0][7]);
            aA[1][0]=fmaf(a1,v0.x,aA[1][0]); aA[1][1]=fmaf(a1,v0.y,aA[1][1]);
            aA[1][2]=fmaf(a1,v0.z,aA[1][2]); aA[1][3]=fmaf(a1,v0.w,aA[1][3]);
            aA[1][4]=fmaf(a1,v1.x,aA[1][4]); aA[1][5]=fmaf(a1,v1.y,aA[1][5]);
            aA[1][6]=fmaf(a1,v1.z,aA[1][6]); aA[1][7]=fmaf(a1,v1.w,aA[1][7]);
        }
        for (int d = 0; d < 64; d++) {
            float q0 = sQ[rr * 65 + d];
            float q1 = sQ[(rr + 1) * 65 + d];
            cqf0 = fmaf(q0, szf[d], cqf0);
            cqf1 = fmaf(q1, szf[d], cqf1);
            cqb0 = fmaf(q0, szb[d], cqb0);
            cqb1 = fmaf(q1, szb[d], cqb1);
            float4 f0 = *(const float4*)(sSf + d * 68 + c0);
            float4 f1 = *(const float4*)(sSf + d * 68 + c0 + 4);
            float4 b0 = *(const float4*)(sSb + d * 68 + c0);
            float4 b1 = *(const float4*)(sSb + d * 68 + c0 + 4);
            aIf[0][0]=fmaf(q0,f0.x,aIf[0][0]); aIf[0][1]=fmaf(q0,f0.y,aIf[0][1]);
            aIf[0][2]=fmaf(q0,f0.z,aIf[0][2]); aIf[0][3]=fmaf(q0,f0.w,aIf[0][3]);
            aIf[0][4]=fmaf(q0,f1.x,aIf[0][4]); aIf[0][5]=fmaf(q0,f1.y,aIf[0][5]);
            aIf[0][6]=fmaf(q0,f1.z,aIf[0][6]); aIf[0][7]=fmaf(q0,f1.w,aIf[0][7]);
            aIf[1][0]=fmaf(q1,f0.x,aIf[1][0]); aIf[1][1]=fmaf(q1,f0.y,aIf[1][1]);
            aIf[1][2]=fmaf(q1,f0.z,aIf[1][2]); aIf[1][3]=fmaf(q1,f0.w,aIf[1][3]);
            aIf[1][4]=fmaf(q1,f1.x,aIf[1][4]); aIf[1][5]=fmaf(q1,f1.y,aIf[1][5]);
            aIf[1][6]=fmaf(q1,f1.z,aIf[1][6]); aIf[1][7]=fmaf(q1,f1.w,aIf[1][7]);
            aIb[0][0]=fmaf(q0,b0.x,aIb[0][0]); aIb[0][1]=fmaf(q0,b0.y,aIb[0][1]);
            aIb[0][2]=fmaf(q0,b0.z,aIb[0][2]); aIb[0][3]=fmaf(q0,b0.w,aIb[0][3]);
            aIb[0][4]=fmaf(q0,b1.x,aIb[0][4]); aIb[0][5]=fmaf(q0,b1.y,aIb[0][5]);
            aIb[0][6]=fmaf(q0,b1.z,aIb[0][6]); aIb[0][7]=fmaf(q0,b1.w,aIb[0][7]);
            aIb[1][0]=fmaf(q1,b0.x,aIb[1][0]); aIb[1][1]=fmaf(q1,b0.y,aIb[1][1]);
            aIb[1][2]=fmaf(q1,b0.z,aIb[1][2]); aIb[1][3]=fmaf(q1,b0.w,aIb[1][3]);
            aIb[1][4]=fmaf(q1,b1.x,aIb[1][4]); aIb[1][5]=fmaf(q1,b1.y,aIb[1][5]);
            aIb[1][6]=fmaf(q1,b1.z,aIb[1][6]); aIb[1][7]=fmaf(q1,b1.w,aIb[1][7]);
        }

        int b = bh >> 3;
#pragma unroll
        for (int i = 0; i < 2; i++) {
            int r = rr + i;
            int t = j * CH_ + r;
            float lf = slp[r + 1];
            float lb = slp[CH_ - r];
            float cden = (i ? cs1 : cs0)
                       + lf * (i ? cqf1 : cqf0)
                       + lb * (i ? cqb1 : cqb0);
            float inv = 1.f / fmaxf(cden, 1e-6f);
            uint32_t hp[4], lp[4];
#pragma unroll
            for (int u = 0; u < 4; u++){
                float y0 = (aA[i][2*u]   + lf*aIf[i][2*u]   + lb*aIb[i][2*u]  ) * inv;
                float y1 = (aA[i][2*u+1] + lf*aIf[i][2*u+1] + lb*aIb[i][2*u+1]) * inv;
                float l0, l1;
                hp[u] = pack2h(y0, y1, &l0, &l1);
                lp[u] = pack2l(l0, l1);
            }
            size_t dst = ((size_t)(b * T_ + t) * D_) + h * HD_ + c0;
            *(uint4*)(g_ath + dst) = make_uint4(hp[0], hp[1], hp[2], hp[3]);
            *(uint4*)(g_atl + dst) = make_uint4(lp[0], lp[1], lp[2], lp[3]);
        }
    }
}

// ------------------------- launcher ----------------------------------------
extern "C" void kernel_launch(void* const* d_in, const int* in_sizes, int n_in,
                              void* d_out, int out_size)
{
    const float* x    = (const float*)d_in[0];
    const float* Wq   = (const float*)d_in[2];
    const float* Wk   = (const float*)d_in[3];
    const float* Wv   = (const float*)d_in[4];
    const float* Wo   = (const float*)d_in[5];
    const float* bo   = (const float*)d_in[6];
    const float* g1   = (const float*)d_in[7];
    const float* b1   = (const float*)d_in[8];
    const float* g2   = (const float*)d_in[9];
    const float* b2   = (const float*)d_in[10];
    const float* W1   = (const float*)d_in[11];
    const float* bf1  = (const float*)d_in[12];
    const float* W2   = (const float*)d_in[13];
    const float* bf2  = (const float*)d_in[14];
    const float* dlog = (const float*)d_in[15];
    float* out = (float*)d_out;

#define SYM(p, s) cudaGetSymbolAddress((void**)&p, s)
    __half *xnh,*xnl,*ath,*atl,*h2h,*h2l,*f1h,*f1l;
    __half *wqkvh,*woh,*w1h,*w2h;
    float *QKV,*x2;
    SYM(xnh,g_xnh); SYM(xnl,g_xnl); SYM(ath,g_ath); SYM(atl,g_atl);
    SYM(h2h,g_h2h); SYM(h2l,g_h2l); SYM(f1h,g_f1h); SYM(f1l,g_f1l);
    SYM(wqkvh,g_wqkvh); SYM(woh,g_woh); SYM(w1h,g_w1h); SYM(w2h,g_w2h);
    SYM(QKV,g_QKV); SYM(x2,g_x2);
#undef SYM

    cudaFuncSetAttribute(tc_gemm<4,512>,   cudaFuncAttributeMaxDynamicSharedMemorySize, GEMM_SMEM);
    cudaFuncSetAttribute(tc_gemm<3,512>,   cudaFuncAttributeMaxDynamicSharedMemorySize, GEMM_SMEM);
    cudaFuncSetAttribute(tc_gemm64<512>,   cudaFuncAttributeMaxDynamicSharedMemorySize, GEMM64_SMEM);
    cudaFuncSetAttribute(tc_gemm64<2048>,  cudaFuncAttributeMaxDynamicSharedMemorySize, GEMM64_SMEM);
    cudaFuncSetAttribute(chunk_comb_kernel,cudaFuncAttributeMaxDynamicSharedMemorySize, CC_SMEM_BYTES);

    dim3 blk(256);
    dim3 gQKV((3*D_) / 128, M_ / 128);  // (12, 32) = 384 CTAs
    dim3 gD64(D_ / 128, M_ / 64);       // (4, 64)  = 256 CTAs
    dim3 gF(F_ / 128, M_ / 128);        // (16, 32) = 512 CTAs

    // 0) all weight splits (hi only, vectorized), one launch
    split_all_kernel<<<786432/256, blk>>>(Wq, Wk, Wv, Wo, W1, W2);
    // 1) LN1 (+fp16 split)
    ln_split_kernel<<<M_, blk>>>(x, g1, b1, xnh, xnl);
    // 2) fused Q/K/V projection (2-pass fp16 emulation)
    tc_gemm<4,512><<<gQKV, blk, GEMM_SMEM>>>(xnh, xnl, wqkvh, 3*D_,
                                             nullptr, QKV, nullptr, nullptr);
    // 3) dual-direction two-level scan + fused chunk/combine
    usum_dual_kernel<<<NBH_ * NCH_, blk>>>(dlog);
    sweep_kernel<<<2 * NBH_ * 16, blk>>>(dlog);
    chunk_comb_kernel<<<NBH_ * NCH_, blk, CC_SMEM_BYTES>>>(dlog);
    // 4) Wo + bias + residual -> fp32 x2
    tc_gemm64<512><<<gD64, blk, GEMM64_SMEM>>>(ath, atl, woh, D_, bo, x, x2);
    // 5) LN2 (+fp16 split)
    ln_split_kernel<<<M_, blk>>>(x2, g2, b2, h2h, h2l);
    // 6) FFN up + GELU -> split fp16
    tc_gemm<3,512><<<gF, blk, GEMM_SMEM>>>(h2h, h2l, w1h, F_, bf1, nullptr, f1h, f1l);
    // 7) FFN down + bias + residual -> final output
    tc_gemm64<2048><<<gD64, blk, GEMM64_SMEM>>>(f1h, f1l, w2h, D_, bf2, x2, out);
}